// round 10
// baseline (speedup 1.0000x reference)
#include <cuda_runtime.h>
#include <cuda_fp16.h>
#include <cstdint>

#define Bsz 8192
#define Dd  512
#define XS  8704           // 17*512 row stride of x / out
#define WSZ 262144         // 512*512 per weight matrix
#define NW  35
#define STG 32768          // per-stage smem: A 16K + B 16K
#define DYN_SMEM (3*STG + 1024)
#define NTQ 2048           // 64 bBase-blocks * 32 z
#define NCLUST 74          // persistent clusters (x4 CTAs = 296 = 148 SMs * 2)

// ---------------- device scratch (allocation-free rule) ----------------
__device__ __align__(256) __half g_xh[Bsz*XS];
__device__ __align__(256) __half g_wh[NW*WSZ];
__device__ __align__(256) __half g_vh[Bsz*Dd];
__device__ __align__(256) __half g_qh[2*Bsz*Dd];     // q then kc (fp16)
__device__ __align__(256) float  s_dotP[16*Bsz*4];   // [z][b][ctaN]

// ---------------- ptx helpers ----------------
__device__ __forceinline__ uint32_t smem_u32(const void* p){
  uint32_t a;
  asm("{ .reg .u64 t; cvta.to.shared.u64 t, %1; cvt.u32.u64 %0, t; }" : "=r"(a) : "l"(p));
  return a;
}
#define CP16(s,g) asm volatile("cp.async.cg.shared.global [%0], [%1], 16;" :: "r"(s), "l"(g))
#define CPCOMMIT() asm volatile("cp.async.commit_group;" ::: "memory")
#define CPWAIT1()  asm volatile("cp.async.wait_group 1;" ::: "memory")
#define CLUSTER_ARRIVE() asm volatile("barrier.cluster.arrive.aligned;" ::: "memory")
#define CLUSTER_WAIT()   asm volatile("barrier.cluster.wait.aligned;" ::: "memory")

__device__ __forceinline__ void ldsm4(uint32_t* r, uint32_t a){
  asm volatile("ldmatrix.sync.aligned.m8n8.x4.shared.b16 {%0,%1,%2,%3}, [%4];"
    : "=r"(r[0]),"=r"(r[1]),"=r"(r[2]),"=r"(r[3]) : "r"(a));
}
#define MMA(c,a,b0,b1) \
  asm volatile("mma.sync.aligned.m16n8k16.row.col.f32.f16.f16.f32 " \
    "{%0,%1,%2,%3},{%4,%5,%6,%7},{%8,%9},{%0,%1,%2,%3};" \
    : "+f"((c)[0]),"+f"((c)[1]),"+f"((c)[2]),"+f"((c)[3]) \
    : "r"((a)[0]),"r"((a)[1]),"r"((a)[2]),"r"((a)[3]),"r"(b0),"r"(b1))

#define SWZ(o) ((o) ^ (((o) >> 3) & 0x70))

// ---------------- fp32 -> fp16 conversion ----------------
__device__ __forceinline__ void cvt8core(const float* __restrict__ s, size_t i,
                                         __half* __restrict__ h){
  float4 a = ((const float4*)s)[2*i], b = ((const float4*)s)[2*i+1];
  __half2 H[4];
  H[0] = __half2(__float2half_rn(a.x), __float2half_rn(a.y));
  H[1] = __half2(__float2half_rn(a.z), __float2half_rn(a.w));
  H[2] = __half2(__float2half_rn(b.x), __float2half_rn(b.y));
  H[3] = __half2(__float2half_rn(b.z), __float2half_rn(b.w));
  ((uint4*)h)[i] = *(uint4*)H;
}

__global__ void cvtAll(const float* __restrict__ x,
                       const float* __restrict__ Wq,  const float* __restrict__ Wkc,
                       const float* __restrict__ Wkp, const float* __restrict__ Wkn,
                       const float* __restrict__ Wfp, const float* __restrict__ Wfn,
                       const float* __restrict__ Wfc){
  const int xB = (Bsz*XS/8)/256;
  const int bid = blockIdx.x;
  if (bid < xB){
    int i = bid*256 + threadIdx.x;
    cvt8core(x, i, g_xh);
  } else {
    int i = (bid - xB)*256 + threadIdx.x;
    int w = i >> 15;
    int j = i & 32767;
    const float* src;
    if      (w == 0)  src = Wq;
    else if (w == 1)  src = Wkc;
    else if (w < 10)  src = Wkp + (size_t)(w-2)*WSZ;
    else if (w < 18)  src = Wkn + (size_t)(w-10)*WSZ;
    else if (w < 26)  src = Wfp + (size_t)(w-18)*WSZ;
    else if (w < 34)  src = Wfn + (size_t)(w-26)*WSZ;
    else              src = Wfc;
    cvt8core(src, j, g_wh + (size_t)w*WSZ);
  }
}

// =======================================================================
// shared building blocks: load one k-chunk (A 128x64 + B 128x64 fp16),
// compute one k-chunk with register double-buffered fragments.
// =======================================================================
__device__ __forceinline__ void load_chunk(const __half* __restrict__ Ah, int lda,
                                           const __half* __restrict__ Wh,
                                           int bBase, int nBase, int kc,
                                           uint32_t base, int tid){
  const int kOff = kc * 64;
  #pragma unroll
  for (int i=0;i<4;i++){
    int idx = i*256 + tid, row = idx>>3, g = idx&7;
    uint32_t sw = SWZ((uint32_t)(row*128 + g*16));
    CP16(base + sw,         Ah + (size_t)(bBase+row)*(size_t)lda + kOff + g*8);
    CP16(base + 16384 + sw, Wh + (size_t)(nBase+row)*Dd + kOff + g*8);
  }
}

__device__ __forceinline__ void compute_chunk(uint32_t aB, uint32_t bB,
    const uint32_t (&aRowOff)[2], const uint32_t (&bRowOff)[4],
    const uint32_t (&selA)[4], const uint32_t (&selB)[4],
    float (&acc)[2][8][4]){
  uint32_t aF[2][2][4], bH[2][2][4];
  ldsm4(aF[0][0], aB + aRowOff[0] + selA[0]);
  ldsm4(aF[0][1], aB + aRowOff[1] + selA[0]);
  ldsm4(bH[0][0], bB + bRowOff[0] + selB[0]);
  ldsm4(bH[0][1], bB + bRowOff[1] + selB[0]);
  #pragma unroll
  for (int q=0;q<4;q++){
    const int cur = q&1, nxt = cur^1;
    ldsm4(bH[1][0], bB + bRowOff[2] + selB[q]);
    ldsm4(bH[1][1], bB + bRowOff[3] + selB[q]);
    #pragma unroll
    for (int mt=0;mt<2;mt++)
      #pragma unroll
      for (int nt=0;nt<2;nt++){
        MMA(acc[mt][nt*2],   aF[cur][mt], bH[0][nt][0], bH[0][nt][1]);
        MMA(acc[mt][nt*2+1], aF[cur][mt], bH[0][nt][2], bH[0][nt][3]);
      }
    if (q < 3){
      ldsm4(aF[nxt][0], aB + aRowOff[0] + selA[q+1]);
      ldsm4(aF[nxt][1], aB + aRowOff[1] + selA[q+1]);
      ldsm4(bH[0][0], bB + bRowOff[0] + selB[q+1]);
      ldsm4(bH[0][1], bB + bRowOff[1] + selB[q+1]);
    }
    #pragma unroll
    for (int mt=0;mt<2;mt++)
      #pragma unroll
      for (int nt=0;nt<2;nt++){
        MMA(acc[mt][4+nt*2],   aF[cur][mt], bH[1][nt][0], bH[1][nt][1]);
        MMA(acc[mt][4+nt*2+1], aF[cur][mt], bH[1][nt][2], bH[1][nt][3]);
      }
  }
}

__device__ __forceinline__ void frag_setup(uint32_t (&aRowOff)[2], uint32_t (&bRowOff)[4],
                                           uint32_t (&selA)[4], uint32_t (&selB)[4]){
  const int tid = threadIdx.x, lane = tid & 31, wid = tid >> 5;
  const int warpM = wid >> 1, warpN = wid & 1;
  #pragma unroll
  for (int i=0;i<2;i++)
    aRowOff[i] = (uint32_t)((warpM*32 + i*16 + (lane&15)) * 128);
  #pragma unroll
  for (int i=0;i<4;i++)
    bRowOff[i] = (uint32_t)((warpN*64 + i*16 + (lane&7) + ((lane&16)>>1)) * 128);
  const int aXb = lane >> 4, bXb = (lane >> 3) & 1, lx = lane & 7;
  #pragma unroll
  for (int q=0;q<4;q++){
    selA[q] = (uint32_t)(((2*q + aXb) ^ lx) << 4);
    selB[q] = (uint32_t)(((2*q + bXb) ^ lx) << 4);
  }
}

// non-persistent 8-chunk mainloop (store / fc kernels)
__device__ __forceinline__ void mainloop8(const __half* __restrict__ Ah, int lda,
                                          const __half* __restrict__ Wh,
                                          int bBase, int nBase, uint32_t dynU,
                                          float (&acc)[2][8][4]){
  const int tid = threadIdx.x;
  uint32_t aRowOff[2], bRowOff[4], selA[4], selB[4];
  frag_setup(aRowOff, bRowOff, selA, selB);
  load_chunk(Ah, lda, Wh, bBase, nBase, 0, dynU, tid);       CPCOMMIT();
  load_chunk(Ah, lda, Wh, bBase, nBase, 1, dynU + STG, tid); CPCOMMIT();
  #pragma unroll
  for (int s=0;s<8;s++){
    CPWAIT1();
    __syncthreads();
    if (s + 2 < 8) load_chunk(Ah, lda, Wh, bBase, nBase, s+2, dynU + ((s+2)%3)*STG, tid);
    CPCOMMIT();
    const uint32_t aB = dynU + (s%3)*STG;
    compute_chunk(aB, aB + 16384, aRowOff, bRowOff, selA, selB, acc);
  }
}

// NORM epilogue (cluster-fused l2 normalization over 4 N-CTAs)
template<bool RES>
__device__ __forceinline__ void norm_epilogue(
    float (&acc)[2][8][4], const float* biasS,
    float (*redS)[2], float* normP, float* scaleS,
    float* outPtr, int ldo, const float* R, int ldr,
    int bBase, int nBase)
{
  const int tid = threadIdx.x, lane = tid & 31, wid = tid >> 5;
  const int warpM = wid >> 1, warpN = wid & 1;
  #pragma unroll
  for (int mt=0;mt<2;mt++){
    const int rl0 = warpM*32 + mt*16 + (lane>>2);
    const float* r0p = RES ? (R + (size_t)(bBase+rl0)*(size_t)ldr) : nullptr;
    const float* r1p = RES ? (r0p + (size_t)8*(size_t)ldr) : nullptr;
    float s0 = 0.f, s1 = 0.f;
    #pragma unroll
    for (int nt=0;nt<8;nt++){
      const int bl = warpN*64 + nt*8 + ((lane&3)<<1);
      const int c  = nBase + bl;
      float bx = biasS[bl], by = biasS[bl+1];
      float v00 = acc[mt][nt][0]+bx, v01 = acc[mt][nt][1]+by;
      float v10 = acc[mt][nt][2]+bx, v11 = acc[mt][nt][3]+by;
      if (RES){
        float2 ra = *(const float2*)(r0p + c);
        float2 rb = *(const float2*)(r1p + c);
        v00 += ra.x; v01 += ra.y; v10 += rb.x; v11 += rb.y;
      }
      acc[mt][nt][0]=v00; acc[mt][nt][1]=v01;
      acc[mt][nt][2]=v10; acc[mt][nt][3]=v11;
      s0 += v00*v00 + v01*v01;
      s1 += v10*v10 + v11*v11;
    }
    s0 += __shfl_xor_sync(0xffffffffu, s0, 1); s0 += __shfl_xor_sync(0xffffffffu, s0, 2);
    s1 += __shfl_xor_sync(0xffffffffu, s1, 1); s1 += __shfl_xor_sync(0xffffffffu, s1, 2);
    if ((lane&3) == 0){ redS[rl0][warpN] = s0; redS[rl0+8][warpN] = s1; }
  }
  __syncthreads();
  if (tid < 128) normP[tid] = redS[tid][0] + redS[tid][1];
  CLUSTER_ARRIVE(); CLUSTER_WAIT();
  if (tid < 128){
    const uint32_t loc = smem_u32(normP) + (uint32_t)tid*4;
    float tot = 0.f;
    #pragma unroll
    for (int r=0;r<4;r++){
      uint32_t rem; float pv;
      asm volatile("mapa.shared::cluster.u32 %0, %1, %2;" : "=r"(rem) : "r"(loc), "r"(r));
      asm volatile("ld.shared::cluster.f32 %0, [%1];" : "=f"(pv) : "r"(rem));
      tot += pv;
    }
    scaleS[tid] = 1.f / fmaxf(sqrtf(tot), 1e-12f);
  }
  CLUSTER_ARRIVE(); CLUSTER_WAIT();
  __syncthreads();
  #pragma unroll
  for (int mt=0;mt<2;mt++){
    const int rl0 = warpM*32 + mt*16 + (lane>>2);
    const float sc0 = scaleS[rl0], sc1 = scaleS[rl0+8];
    float* o0 = outPtr + (size_t)(bBase+rl0)*(size_t)ldo;
    float* o1 = o0 + (size_t)8*(size_t)ldo;
    #pragma unroll
    for (int nt=0;nt<8;nt++){
      const int c = nBase + warpN*64 + nt*8 + ((lane&3)<<1);
      *(float2*)(o0 + c) = make_float2(acc[mt][nt][0]*sc0, acc[mt][nt][1]*sc0);
      *(float2*)(o1 + c) = make_float2(acc[mt][nt][2]*sc1, acc[mt][nt][3]*sc1);
    }
  }
}

// =======================================================================
// q/kc GEMM -> fp16 output, grid (64,4,2)
// =======================================================================
__global__ void __launch_bounds__(256,2) hgemm_store(
    const float* __restrict__ bq, const float* __restrict__ bkc)
{
  const int z = blockIdx.z;
  const __half* Ah = g_xh + 4096;
  const __half* Wh = g_wh + (size_t)z*WSZ;
  const float* bp = (z == 0) ? bq : bkc;
  __half* outPtr = g_qh + (size_t)z*Bsz*Dd;

  const int tid = threadIdx.x, lane = tid & 31, wid = tid >> 5;
  const int warpM = wid >> 1, warpN = wid & 1;
  const int bBase = blockIdx.x * 128, nBase = blockIdx.y * 128;

  extern __shared__ char dsm[];
  const uint32_t dynU = (smem_u32(dsm) + 1023u) & ~1023u;
  __shared__ float biasS[128];
  if (tid < 32) ((float4*)biasS)[tid] = ((const float4*)(bp + nBase))[tid];

  float acc[2][8][4];
  #pragma unroll
  for (int m=0;m<2;m++) for (int n=0;n<8;n++) for (int i=0;i<4;i++) acc[m][n][i]=0.f;

  mainloop8(Ah, XS, Wh, bBase, nBase, dynU, acc);

  #pragma unroll
  for (int mt=0;mt<2;mt++){
    const int rl0 = warpM*32 + mt*16 + (lane>>2);
    __half* o0 = outPtr + (size_t)(bBase+rl0)*Dd;
    __half* o1 = o0 + (size_t)8*Dd;
    #pragma unroll
    for (int nt=0;nt<8;nt++){
      const int bl = warpN*64 + nt*8 + ((lane&3)<<1);
      const int c  = nBase + bl;
      float bx = biasS[bl], by = biasS[bl+1];
      *(__half2*)(o0 + c) = __floats2half2_rn(acc[mt][nt][0]+bx, acc[mt][nt][1]+by);
      *(__half2*)(o1 + c) = __floats2half2_rn(acc[mt][nt][2]+bx, acc[mt][nt][3]+by);
    }
  }
}

// =======================================================================
// persistent DOT+NORM kernel: 74 clusters x 4 CTAs, each cluster iterates
// over (bBase, z) tile-quads with a continuous cp.async pipeline.
// =======================================================================
__global__ void __cluster_dims__(4,1,1) __launch_bounds__(256,2) hgemm_dnp(
    const float* __restrict__ bkp, const float* __restrict__ bkn,
    const float* __restrict__ bfp, const float* __restrict__ bfn,
    float* __restrict__ dotP, float* __restrict__ out)
{
  const int rank = blockIdx.x & 3, cid = blockIdx.x >> 2;
  const int nBase = rank * 128;
  const int tid = threadIdx.x, lane = tid & 31, wid = tid >> 5;
  const int warpM = wid >> 1, warpN = wid & 1;

  extern __shared__ char dsm[];
  const uint32_t dynU = (smem_u32(dsm) + 1023u) & ~1023u;
  __shared__ float biasS[128];
  __shared__ float redS[128][2];
  __shared__ float normP[128];
  __shared__ float scaleS[128];

  uint32_t aRowOff[2], bRowOff[4], selA[4], selB[4];
  frag_setup(aRowOff, bRowOff, selA, selB);

  // load cursor
  int lt = cid, ls = 0;
  const __half *AhL = nullptr, *WhL = nullptr; int bBL = 0;
  auto setLoadTile = [&](int t){
    int z = t & 31; int zw = z & 15; int widx = zw + (zw >= 8 ? 1 : 0);
    AhL = g_xh + widx*Dd;
    WhL = g_wh + (size_t)(((z < 16) ? 2 : 18) + zw)*WSZ;
    bBL = (t >> 5) << 7;
  };
  if (lt < NTQ){
    setLoadTile(lt);
    load_chunk(AhL, XS, WhL, bBL, nBase, 0, dynU,       tid); CPCOMMIT();
    load_chunk(AhL, XS, WhL, bBL, nBase, 1, dynU + STG, tid); CPCOMMIT();
    ls = 2;
  }
  int cb = 0;

  for (int t = cid; t < NTQ; t += NCLUST){
    const int z = t & 31;
    const bool isDot = (z < 16);
    const int zw = z & 15, widx = zw + (zw >= 8 ? 1 : 0);
    const int bBase = (t >> 5) << 7;
    const float* bp = isDot ? ((zw < 8) ? bkp + (size_t)zw*Dd : bkn + (size_t)(zw-8)*Dd)
                            : ((zw < 8) ? bfp + (size_t)zw*Dd : bfn + (size_t)(zw-8)*Dd);

    float acc[2][8][4];
    #pragma unroll
    for (int m=0;m<2;m++) for (int n=0;n<8;n++) for (int i=0;i<4;i++) acc[m][n][i]=0.f;

    #pragma unroll
    for (int s=0;s<8;s++){
      CPWAIT1();
      __syncthreads();
      if (s == 0 && tid < 32)
        ((float4*)biasS)[tid] = ((const float4*)(bp + nBase))[tid];
      if (lt < NTQ){
        load_chunk(AhL, XS, WhL, bBL, nBase, ls, dynU + (uint32_t)((cb+2)%3)*STG, tid);
        if (++ls == 8){ ls = 0; lt += NCLUST; if (lt < NTQ) setLoadTile(lt); }
      }
      CPCOMMIT();
      const uint32_t aB = dynU + (uint32_t)cb*STG;
      compute_chunk(aB, aB + 16384, aRowOff, bRowOff, selA, selB, acc);
      cb = (cb + 1 == 3) ? 0 : cb + 1;
    }

    if (isDot){
      #pragma unroll
      for (int mt=0;mt<2;mt++){
        const int rl0 = warpM*32 + mt*16 + (lane>>2);
        const __half* q0 = g_qh + (size_t)(bBase+rl0)*Dd;
        const __half* q1 = q0 + (size_t)8*Dd;
        float s0 = 0.f, s1 = 0.f;
        #pragma unroll
        for (int nt=0;nt<8;nt++){
          const int bl = warpN*64 + nt*8 + ((lane&3)<<1);
          const int c  = nBase + bl;
          float bx = biasS[bl], by = biasS[bl+1];
          float2 qa = __half22float2(*(const __half2*)(q0 + c));
          float2 qb = __half22float2(*(const __half2*)(q1 + c));
          s0 += (acc[mt][nt][0]+bx)*qa.x + (acc[mt][nt][1]+by)*qa.y;
          s1 += (acc[mt][nt][2]+bx)*qb.x + (acc[mt][nt][3]+by)*qb.y;
        }
        s0 += __shfl_xor_sync(0xffffffffu, s0, 1); s0 += __shfl_xor_sync(0xffffffffu, s0, 2);
        s1 += __shfl_xor_sync(0xffffffffu, s1, 1); s1 += __shfl_xor_sync(0xffffffffu, s1, 2);
        if ((lane&3) == 0){ redS[rl0][warpN] = s0; redS[rl0+8][warpN] = s1; }
      }
      __syncthreads();
      if (tid < 128){
        float p = redS[tid][0] + redS[tid][1];
        dotP[((size_t)z*Bsz + bBase + tid)*4 + rank] = p;
      }
    } else {
      norm_epilogue<false>(acc, biasS, redS, normP, scaleS,
                           out + (size_t)widx*Dd, XS, nullptr, 0, bBase, nBase);
    }
  }
}

// =======================================================================
// fc GEMM (+residual xc, cluster-fused norm), grid (64,4,1)
// =======================================================================
__global__ void __cluster_dims__(1,4,1) __launch_bounds__(256,2) hgemm_fc(
    const float* __restrict__ bfc, const float* __restrict__ x,
    float* __restrict__ out)
{
  const int tid = threadIdx.x;
  const int bBase = blockIdx.x * 128, nBase = blockIdx.y * 128;

  extern __shared__ char dsm[];
  const uint32_t dynU = (smem_u32(dsm) + 1023u) & ~1023u;
  __shared__ float biasS[128];
  __shared__ float redS[128][2];
  __shared__ float normP[128];
  __shared__ float scaleS[128];
  if (tid < 32) ((float4*)biasS)[tid] = ((const float4*)(bfc + nBase))[tid];

  float acc[2][8][4];
  #pragma unroll
  for (int m=0;m<2;m++) for (int n=0;n<8;n++) for (int i=0;i<4;i++) acc[m][n][i]=0.f;

  mainloop8(g_vh, Dd, g_wh + (size_t)34*WSZ, bBase, nBase, dynU, acc);

  norm_epilogue<true>(acc, biasS, redS, normP, scaleS,
                      out + 4096, XS, x + 4096, XS, bBase, nBase);
}

// =======================================================================
// mix: attn = q.kc; vh = fp16(l2norm(xc*attn + sum_w ap*xp_w + an*xn_w))
// q/kc read as fp16; windows from fp16 xh; xc from fp32 x.
// =======================================================================
__global__ void mix_kernel(const float* __restrict__ x,
                           const float* __restrict__ dotP)
{
  __shared__ float sb[4];
  const int b = blockIdx.x, t = threadIdx.x;
  const __half* xhr = g_xh + (size_t)b*XS;

  uint2 qv = *(const uint2*)(g_qh + (size_t)b*Dd + t*4);
  uint2 kv = *(const uint2*)(g_qh + (size_t)(Bsz + b)*Dd + t*4);
  float2 qa = __half22float2(*(__half2*)&qv.x);
  float2 qb = __half22float2(*(__half2*)&qv.y);
  float2 ka = __half22float2(*(__half2*)&kv.x);
  float2 kb = __half22float2(*(__half2*)&kv.y);
  float part = qa.x*ka.x + qa.y*ka.y + qb.x*kb.x + qb.y*kb.y;
  #pragma unroll
  for (int o=16;o;o>>=1) part += __shfl_xor_sync(0xffffffffu, part, o);
  if ((t & 31) == 0) sb[t>>5] = part;
  __syncthreads();
  const float attn = sb[0] + sb[1] + sb[2] + sb[3];
  __syncthreads();

  float4 xc4 = ((const float4*)(x + (size_t)b*XS + 4096))[t];
  float4 acc;
  acc.x = xc4.x*attn; acc.y = xc4.y*attn; acc.z = xc4.z*attn; acc.w = xc4.w*attn;
  #pragma unroll
  for (int w=0;w<8;w++){
    float4 pa = *(const float4*)(dotP + ((size_t)w*Bsz + b)*4);
    float aw = pa.x + pa.y + pa.z + pa.w;
    uint2 up = *(const uint2*)(xhr + w*512 + t*4);
    float2 p0 = __half22float2(*(__half2*)&up.x);
    float2 p1 = __half22float2(*(__half2*)&up.y);
    acc.x += aw*p0.x; acc.y += aw*p0.y; acc.z += aw*p1.x; acc.w += aw*p1.y;
    float4 pn = *(const float4*)(dotP + ((size_t)(8+w)*Bsz + b)*4);
    float nw = pn.x + pn.y + pn.z + pn.w;
    uint2 un = *(const uint2*)(xhr + (9+w)*512 + t*4);
    float2 n0 = __half22float2(*(__half2*)&un.x);
    float2 n1 = __half22float2(*(__half2*)&un.y);
    acc.x += nw*n0.x; acc.y += nw*n0.y; acc.z += nw*n1.x; acc.w += nw*n1.y;
  }
  float ss = acc.x*acc.x + acc.y*acc.y + acc.z*acc.z + acc.w*acc.w;
  #pragma unroll
  for (int o=16;o;o>>=1) ss += __shfl_xor_sync(0xffffffffu, ss, o);
  if ((t & 31) == 0) sb[t>>5] = ss;
  __syncthreads();
  float tot = sb[0] + sb[1] + sb[2] + sb[3];
  float sc = 1.f / fmaxf(sqrtf(tot), 1e-12f);
  __half2 h0 = __floats2half2_rn(acc.x*sc, acc.y*sc);
  __half2 h1 = __floats2half2_rn(acc.z*sc, acc.w*sc);
  uint2 o; o.x = *(uint32_t*)&h0; o.y = *(uint32_t*)&h1;
  *(uint2*)(g_vh + (size_t)b*Dd + t*4) = o;
}

// =======================================================================
extern "C" void kernel_launch(void* const* d_in, const int* in_sizes, int n_in,
                              void* d_out, int out_size)
{
  const float* x   = (const float*)d_in[0];
  const float* Wq  = (const float*)d_in[1];
  const float* bq  = (const float*)d_in[2];
  const float* Wkc = (const float*)d_in[3];
  const float* bkc = (const float*)d_in[4];
  const float* Wkp = (const float*)d_in[5];
  const float* bkp = (const float*)d_in[6];
  const float* Wkn = (const float*)d_in[7];
  const float* bkn = (const float*)d_in[8];
  const float* Wfp = (const float*)d_in[9];
  const float* bfp = (const float*)d_in[10];
  const float* Wfn = (const float*)d_in[11];
  const float* bfn = (const float*)d_in[12];
  const float* Wfc = (const float*)d_in[13];
  const float* bfc = (const float*)d_in[14];
  float* out = (float*)d_out;

  float *dotP;
  cudaGetSymbolAddress((void**)&dotP, s_dotP);

  cudaFuncSetAttribute(hgemm_store, cudaFuncAttributeMaxDynamicSharedMemorySize, DYN_SMEM);
  cudaFuncSetAttribute(hgemm_dnp,   cudaFuncAttributeMaxDynamicSharedMemorySize, DYN_SMEM);
  cudaFuncSetAttribute(hgemm_fc,    cudaFuncAttributeMaxDynamicSharedMemorySize, DYN_SMEM);

  // [0] x + all 35 weights -> fp16
  const int xBlocks = (Bsz*XS/8)/256;          // 34816
  const int wBlocks = (NW*(WSZ/8))/256;        // 4480
  cvtAll<<<xBlocks + wBlocks, 256>>>(x, Wq, Wkc, Wkp, Wkn, Wfp, Wfn, Wfc);

  // [1] q / kc (fp16 outputs)
  hgemm_store<<<dim3(64,4,2), 256, DYN_SMEM>>>(bq, bkc);

  // [2] persistent DOT (z 0..15) + NORM (z 16..31)
  hgemm_dnp<<<dim3(4*NCLUST,1,1), 256, DYN_SMEM>>>(bkp, bkn, bfp, bfn, dotP, out);

  // [3] mix -> vh (fp16 direct)
  mix_kernel<<<Bsz, 128>>>(x, dotP);

  // [4] fc (+ residual xc), cluster-fused norm
  hgemm_fc<<<dim3(64,4,1), 256, DYN_SMEM>>>(bfc, x, out);
}

// round 11
// speedup vs baseline: 1.1772x; 1.1772x over previous
#include <cuda_runtime.h>
#include <cuda_fp16.h>
#include <cstdint>

#define Bsz 8192
#define Dd  512
#define XS  8704           // 17*512 row stride of x / out
#define WSZ 262144         // 512*512 per weight matrix
#define NW  35
#define STG 32768          // per-stage smem: A 16K + B 16K
#define DYN_SMEM (3*STG + 1024)

// ---------------- device scratch (allocation-free rule) ----------------
__device__ __align__(256) __half g_xh[Bsz*XS];
__device__ __align__(256) __half g_wh[NW*WSZ];
__device__ __align__(256) __half g_vh[Bsz*Dd];
__device__ __align__(256) __half g_qh[2*Bsz*Dd];     // q then kc (fp16)
__device__ __align__(256) float  s_dotP[16*Bsz*4];   // [z][b][ctaN]

// ---------------- ptx helpers ----------------
__device__ __forceinline__ uint32_t smem_u32(const void* p){
  uint32_t a;
  asm("{ .reg .u64 t; cvta.to.shared.u64 t, %1; cvt.u32.u64 %0, t; }" : "=r"(a) : "l"(p));
  return a;
}
#define CP16(s,g) asm volatile("cp.async.cg.shared.global [%0], [%1], 16;" :: "r"(s), "l"(g))
#define CPCOMMIT() asm volatile("cp.async.commit_group;" ::: "memory")
#define CPWAIT1()  asm volatile("cp.async.wait_group 1;" ::: "memory")
#define CLUSTER_ARRIVE() asm volatile("barrier.cluster.arrive.aligned;" ::: "memory")
#define CLUSTER_WAIT()   asm volatile("barrier.cluster.wait.aligned;" ::: "memory")

__device__ __forceinline__ void ldsm4(uint32_t* r, uint32_t a){
  asm volatile("ldmatrix.sync.aligned.m8n8.x4.shared.b16 {%0,%1,%2,%3}, [%4];"
    : "=r"(r[0]),"=r"(r[1]),"=r"(r[2]),"=r"(r[3]) : "r"(a));
}
#define MMA(c,a,b0,b1) \
  asm volatile("mma.sync.aligned.m16n8k16.row.col.f32.f16.f16.f32 " \
    "{%0,%1,%2,%3},{%4,%5,%6,%7},{%8,%9},{%0,%1,%2,%3};" \
    : "+f"((c)[0]),"+f"((c)[1]),"+f"((c)[2]),"+f"((c)[3]) \
    : "r"((a)[0]),"r"((a)[1]),"r"((a)[2]),"r"((a)[3]),"r"(b0),"r"(b1))

#define SWZ(o) ((o) ^ (((o) >> 3) & 0x70))

// ---------------- fp32 -> fp16 conversion ----------------
__device__ __forceinline__ void cvt8core(const float* __restrict__ s, size_t i,
                                         __half* __restrict__ h){
  float4 a = ((const float4*)s)[2*i], b = ((const float4*)s)[2*i+1];
  __half2 H[4];
  H[0] = __half2(__float2half_rn(a.x), __float2half_rn(a.y));
  H[1] = __half2(__float2half_rn(a.z), __float2half_rn(a.w));
  H[2] = __half2(__float2half_rn(b.x), __float2half_rn(b.y));
  H[3] = __half2(__float2half_rn(b.z), __float2half_rn(b.w));
  ((uint4*)h)[i] = *(uint4*)H;
}

__global__ void cvtAll(const float* __restrict__ x,
                       const float* __restrict__ Wq,  const float* __restrict__ Wkc,
                       const float* __restrict__ Wkp, const float* __restrict__ Wkn,
                       const float* __restrict__ Wfp, const float* __restrict__ Wfn,
                       const float* __restrict__ Wfc){
  const int xB = (Bsz*XS/8)/256;
  const int bid = blockIdx.x;
  if (bid < xB){
    int i = bid*256 + threadIdx.x;
    cvt8core(x, i, g_xh);
  } else {
    int i = (bid - xB)*256 + threadIdx.x;
    int w = i >> 15;
    int j = i & 32767;
    const float* src;
    if      (w == 0)  src = Wq;
    else if (w == 1)  src = Wkc;
    else if (w < 10)  src = Wkp + (size_t)(w-2)*WSZ;
    else if (w < 18)  src = Wkn + (size_t)(w-10)*WSZ;
    else if (w < 26)  src = Wfp + (size_t)(w-18)*WSZ;
    else if (w < 34)  src = Wfn + (size_t)(w-26)*WSZ;
    else              src = Wfc;
    cvt8core(src, j, g_wh + (size_t)w*WSZ);
  }
}

// =======================================================================
// building blocks
// =======================================================================
__device__ __forceinline__ void load_chunk(const __half* __restrict__ Ah, int lda,
                                           const __half* __restrict__ Wh,
                                           int bBase, int nBase, int kc,
                                           uint32_t base, int tid){
  const int kOff = kc * 64;
  #pragma unroll
  for (int i=0;i<4;i++){
    int idx = i*256 + tid, row = idx>>3, g = idx&7;
    uint32_t sw = SWZ((uint32_t)(row*128 + g*16));
    CP16(base + sw,         Ah + (size_t)(bBase+row)*(size_t)lda + kOff + g*8);
    CP16(base + 16384 + sw, Wh + (size_t)(nBase+row)*Dd + kOff + g*8);
  }
}

__device__ __forceinline__ void compute_chunk(uint32_t aB, uint32_t bB,
    const uint32_t (&aRowOff)[2], const uint32_t (&bRowOff)[4],
    const uint32_t (&selA)[4], const uint32_t (&selB)[4],
    float (&acc)[2][8][4]){
  uint32_t aF[2][2][4], bH[2][2][4];
  ldsm4(aF[0][0], aB + aRowOff[0] + selA[0]);
  ldsm4(aF[0][1], aB + aRowOff[1] + selA[0]);
  ldsm4(bH[0][0], bB + bRowOff[0] + selB[0]);
  ldsm4(bH[0][1], bB + bRowOff[1] + selB[0]);
  #pragma unroll
  for (int q=0;q<4;q++){
    const int cur = q&1, nxt = cur^1;
    ldsm4(bH[1][0], bB + bRowOff[2] + selB[q]);
    ldsm4(bH[1][1], bB + bRowOff[3] + selB[q]);
    #pragma unroll
    for (int mt=0;mt<2;mt++)
      #pragma unroll
      for (int nt=0;nt<2;nt++){
        MMA(acc[mt][nt*2],   aF[cur][mt], bH[0][nt][0], bH[0][nt][1]);
        MMA(acc[mt][nt*2+1], aF[cur][mt], bH[0][nt][2], bH[0][nt][3]);
      }
    if (q < 3){
      ldsm4(aF[nxt][0], aB + aRowOff[0] + selA[q+1]);
      ldsm4(aF[nxt][1], aB + aRowOff[1] + selA[q+1]);
      ldsm4(bH[0][0], bB + bRowOff[0] + selB[q+1]);
      ldsm4(bH[0][1], bB + bRowOff[1] + selB[q+1]);
    }
    #pragma unroll
    for (int mt=0;mt<2;mt++)
      #pragma unroll
      for (int nt=0;nt<2;nt++){
        MMA(acc[mt][4+nt*2],   aF[cur][mt], bH[1][nt][0], bH[1][nt][1]);
        MMA(acc[mt][4+nt*2+1], aF[cur][mt], bH[1][nt][2], bH[1][nt][3]);
      }
  }
}

__device__ __forceinline__ void frag_setup(uint32_t (&aRowOff)[2], uint32_t (&bRowOff)[4],
                                           uint32_t (&selA)[4], uint32_t (&selB)[4]){
  const int tid = threadIdx.x, lane = tid & 31, wid = tid >> 5;
  const int warpM = wid >> 1, warpN = wid & 1;
  #pragma unroll
  for (int i=0;i<2;i++)
    aRowOff[i] = (uint32_t)((warpM*32 + i*16 + (lane&15)) * 128);
  #pragma unroll
  for (int i=0;i<4;i++)
    bRowOff[i] = (uint32_t)((warpN*64 + i*16 + (lane&7) + ((lane&16)>>1)) * 128);
  const int aXb = lane >> 4, bXb = (lane >> 3) & 1, lx = lane & 7;
  #pragma unroll
  for (int q=0;q<4;q++){
    selA[q] = (uint32_t)(((2*q + aXb) ^ lx) << 4);
    selB[q] = (uint32_t)(((2*q + bXb) ^ lx) << 4);
  }
}

// non-persistent 8-chunk mainloop (store / fc kernels)
__device__ __forceinline__ void mainloop8(const __half* __restrict__ Ah, int lda,
                                          const __half* __restrict__ Wh,
                                          int bBase, int nBase, uint32_t dynU,
                                          float (&acc)[2][8][4]){
  const int tid = threadIdx.x;
  uint32_t aRowOff[2], bRowOff[4], selA[4], selB[4];
  frag_setup(aRowOff, bRowOff, selA, selB);
  load_chunk(Ah, lda, Wh, bBase, nBase, 0, dynU, tid);       CPCOMMIT();
  load_chunk(Ah, lda, Wh, bBase, nBase, 1, dynU + STG, tid); CPCOMMIT();
  #pragma unroll
  for (int s=0;s<8;s++){
    CPWAIT1();
    __syncthreads();
    if (s + 2 < 8) load_chunk(Ah, lda, Wh, bBase, nBase, s+2, dynU + ((s+2)%3)*STG, tid);
    CPCOMMIT();
    const uint32_t aB = dynU + (s%3)*STG;
    compute_chunk(aB, aB + 16384, aRowOff, bRowOff, selA, selB, acc);
  }
}

// NORM epilogue (cluster-fused l2 normalization over 4 N-CTAs)
template<bool RES>
__device__ __forceinline__ void norm_epilogue(
    float (&acc)[2][8][4], const float* biasS,
    float (*redS)[2], float* normP, float* scaleS,
    float* outPtr, int ldo, const float* R, int ldr,
    int bBase, int nBase)
{
  const int tid = threadIdx.x, lane = tid & 31, wid = tid >> 5;
  const int warpM = wid >> 1, warpN = wid & 1;
  #pragma unroll
  for (int mt=0;mt<2;mt++){
    const int rl0 = warpM*32 + mt*16 + (lane>>2);
    const float* r0p = RES ? (R + (size_t)(bBase+rl0)*(size_t)ldr) : nullptr;
    const float* r1p = RES ? (r0p + (size_t)8*(size_t)ldr) : nullptr;
    float s0 = 0.f, s1 = 0.f;
    #pragma unroll
    for (int nt=0;nt<8;nt++){
      const int bl = warpN*64 + nt*8 + ((lane&3)<<1);
      const int c  = nBase + bl;
      float bx = biasS[bl], by = biasS[bl+1];
      float v00 = acc[mt][nt][0]+bx, v01 = acc[mt][nt][1]+by;
      float v10 = acc[mt][nt][2]+bx, v11 = acc[mt][nt][3]+by;
      if (RES){
        float2 ra = *(const float2*)(r0p + c);
        float2 rb = *(const float2*)(r1p + c);
        v00 += ra.x; v01 += ra.y; v10 += rb.x; v11 += rb.y;
      }
      acc[mt][nt][0]=v00; acc[mt][nt][1]=v01;
      acc[mt][nt][2]=v10; acc[mt][nt][3]=v11;
      s0 += v00*v00 + v01*v01;
      s1 += v10*v10 + v11*v11;
    }
    s0 += __shfl_xor_sync(0xffffffffu, s0, 1); s0 += __shfl_xor_sync(0xffffffffu, s0, 2);
    s1 += __shfl_xor_sync(0xffffffffu, s1, 1); s1 += __shfl_xor_sync(0xffffffffu, s1, 2);
    if ((lane&3) == 0){ redS[rl0][warpN] = s0; redS[rl0+8][warpN] = s1; }
  }
  __syncthreads();
  if (tid < 128) normP[tid] = redS[tid][0] + redS[tid][1];
  CLUSTER_ARRIVE(); CLUSTER_WAIT();
  if (tid < 128){
    const uint32_t loc = smem_u32(normP) + (uint32_t)tid*4;
    float tot = 0.f;
    #pragma unroll
    for (int r=0;r<4;r++){
      uint32_t rem; float pv;
      asm volatile("mapa.shared::cluster.u32 %0, %1, %2;" : "=r"(rem) : "r"(loc), "r"(r));
      asm volatile("ld.shared::cluster.f32 %0, [%1];" : "=f"(pv) : "r"(rem));
      tot += pv;
    }
    scaleS[tid] = 1.f / fmaxf(sqrtf(tot), 1e-12f);
  }
  CLUSTER_ARRIVE(); CLUSTER_WAIT();
  __syncthreads();
  #pragma unroll
  for (int mt=0;mt<2;mt++){
    const int rl0 = warpM*32 + mt*16 + (lane>>2);
    const float sc0 = scaleS[rl0], sc1 = scaleS[rl0+8];
    float* o0 = outPtr + (size_t)(bBase+rl0)*(size_t)ldo;
    float* o1 = o0 + (size_t)8*(size_t)ldo;
    #pragma unroll
    for (int nt=0;nt<8;nt++){
      const int c = nBase + warpN*64 + nt*8 + ((lane&3)<<1);
      *(float2*)(o0 + c) = make_float2(acc[mt][nt][0]*sc0, acc[mt][nt][1]*sc0);
      *(float2*)(o1 + c) = make_float2(acc[mt][nt][2]*sc1, acc[mt][nt][3]*sc1);
    }
  }
}

// =======================================================================
// q/kc GEMM -> fp16 output, grid (64,4,2)
// =======================================================================
__global__ void __launch_bounds__(256,2) hgemm_store(
    const float* __restrict__ bq, const float* __restrict__ bkc)
{
  const int z = blockIdx.z;
  const __half* Ah = g_xh + 4096;
  const __half* Wh = g_wh + (size_t)z*WSZ;
  const float* bp = (z == 0) ? bq : bkc;
  __half* outPtr = g_qh + (size_t)z*Bsz*Dd;

  const int tid = threadIdx.x, lane = tid & 31, wid = tid >> 5;
  const int warpM = wid >> 1, warpN = wid & 1;
  const int bBase = blockIdx.x * 128, nBase = blockIdx.y * 128;

  extern __shared__ char dsm[];
  const uint32_t dynU = (smem_u32(dsm) + 1023u) & ~1023u;
  __shared__ float biasS[128];
  if (tid < 32) ((float4*)biasS)[tid] = ((const float4*)(bp + nBase))[tid];

  float acc[2][8][4];
  #pragma unroll
  for (int m=0;m<2;m++) for (int n=0;n<8;n++) for (int i=0;i<4;i++) acc[m][n][i]=0.f;

  mainloop8(Ah, XS, Wh, bBase, nBase, dynU, acc);

  #pragma unroll
  for (int mt=0;mt<2;mt++){
    const int rl0 = warpM*32 + mt*16 + (lane>>2);
    __half* o0 = outPtr + (size_t)(bBase+rl0)*Dd;
    __half* o1 = o0 + (size_t)8*Dd;
    #pragma unroll
    for (int nt=0;nt<8;nt++){
      const int bl = warpN*64 + nt*8 + ((lane&3)<<1);
      const int c  = nBase + bl;
      float bx = biasS[bl], by = biasS[bl+1];
      *(__half2*)(o0 + c) = __floats2half2_rn(acc[mt][nt][0]+bx, acc[mt][nt][1]+by);
      *(__half2*)(o1 + c) = __floats2half2_rn(acc[mt][nt][2]+bx, acc[mt][nt][3]+by);
    }
  }
}

// =======================================================================
// paired DOT+NORM kernel: grid (64,4,16), cluster (1,4,1).
// Each CTA runs a continuous 16-chunk pipeline over the SAME A window:
// chunks 0-7 with Wk (-> DOT epilogue), chunks 8-15 with Wf (-> NORM).
// =======================================================================
__global__ void __cluster_dims__(1,4,1) __launch_bounds__(256,2) hgemm_dn(
    const float* __restrict__ bkp, const float* __restrict__ bkn,
    const float* __restrict__ bfp, const float* __restrict__ bfn,
    float* __restrict__ dotP, float* __restrict__ out)
{
  const int zw = blockIdx.z;                       // 0..15 window slot
  const int widx = zw + (zw >= 8 ? 1 : 0);         // skip center
  const __half* Ah = g_xh + widx*Dd;
  const __half* Wk = g_wh + (size_t)(2  + zw)*WSZ;
  const __half* Wf = g_wh + (size_t)(18 + zw)*WSZ;
  const float* bpK = (zw < 8) ? bkp + (size_t)zw*Dd : bkn + (size_t)(zw-8)*Dd;
  const float* bpF = (zw < 8) ? bfp + (size_t)zw*Dd : bfn + (size_t)(zw-8)*Dd;

  const int tid = threadIdx.x, lane = tid & 31, wid = tid >> 5;
  const int warpM = wid >> 1, warpN = wid & 1;
  const int bBase = blockIdx.x * 128, nBase = blockIdx.y * 128;

  extern __shared__ char dsm[];
  const uint32_t dynU = (smem_u32(dsm) + 1023u) & ~1023u;
  __shared__ float biasK[128];
  __shared__ float biasF[128];
  __shared__ float redS[128][2];
  __shared__ float normP[128];
  __shared__ float scaleS[128];
  if (tid < 32){
    ((float4*)biasK)[tid] = ((const float4*)(bpK + nBase))[tid];
    ((float4*)biasF)[tid] = ((const float4*)(bpF + nBase))[tid];
  }

  uint32_t aRowOff[2], bRowOff[4], selA[4], selB[4];
  frag_setup(aRowOff, bRowOff, selA, selB);

  float acc[2][8][4];
  #pragma unroll
  for (int m=0;m<2;m++) for (int n=0;n<8;n++) for (int i=0;i<4;i++) acc[m][n][i]=0.f;

  // continuous 16-chunk pipeline (chunk c: kc=c&7, W = c<8 ? Wk : Wf)
  load_chunk(Ah, XS, Wk, bBase, nBase, 0, dynU,       tid); CPCOMMIT();
  load_chunk(Ah, XS, Wk, bBase, nBase, 1, dynU + STG, tid); CPCOMMIT();

  #pragma unroll
  for (int c = 0; c < 16; c++){
    CPWAIT1();
    __syncthreads();
    if (c + 2 < 16){
      const int lc = c + 2;
      load_chunk(Ah, XS, (lc < 8) ? Wk : Wf, bBase, nBase, lc & 7,
                 dynU + (uint32_t)(lc % 3)*STG, tid);
    }
    CPCOMMIT();
    const uint32_t aB = dynU + (uint32_t)(c % 3)*STG;
    compute_chunk(aB, aB + 16384, aRowOff, bRowOff, selA, selB, acc);

    if (c == 7){
      // ---- DOT epilogue (hidden behind in-flight chunk 8/9 loads) ----
      #pragma unroll
      for (int mt=0;mt<2;mt++){
        const int rl0 = warpM*32 + mt*16 + (lane>>2);
        const __half* q0 = g_qh + (size_t)(bBase+rl0)*Dd;
        const __half* q1 = q0 + (size_t)8*Dd;
        float s0 = 0.f, s1 = 0.f;
        #pragma unroll
        for (int nt=0;nt<8;nt++){
          const int bl = warpN*64 + nt*8 + ((lane&3)<<1);
          const int cc = nBase + bl;
          float bx = biasK[bl], by = biasK[bl+1];
          float2 qa = __half22float2(*(const __half2*)(q0 + cc));
          float2 qb = __half22float2(*(const __half2*)(q1 + cc));
          s0 += (acc[mt][nt][0]+bx)*qa.x + (acc[mt][nt][1]+by)*qa.y;
          s1 += (acc[mt][nt][2]+bx)*qb.x + (acc[mt][nt][3]+by)*qb.y;
        }
        s0 += __shfl_xor_sync(0xffffffffu, s0, 1); s0 += __shfl_xor_sync(0xffffffffu, s0, 2);
        s1 += __shfl_xor_sync(0xffffffffu, s1, 1); s1 += __shfl_xor_sync(0xffffffffu, s1, 2);
        if ((lane&3) == 0){ redS[rl0][warpN] = s0; redS[rl0+8][warpN] = s1; }
      }
      __syncthreads();
      if (tid < 128){
        float p = redS[tid][0] + redS[tid][1];
        dotP[((size_t)zw*Bsz + bBase + tid)*4 + blockIdx.y] = p;
      }
      // reset accumulators for the NORM GEMM
      #pragma unroll
      for (int m=0;m<2;m++) for (int n=0;n<8;n++) for (int i=0;i<4;i++) acc[m][n][i]=0.f;
    }
  }

  norm_epilogue<false>(acc, biasF, redS, normP, scaleS,
                       out + (size_t)widx*Dd, XS, nullptr, 0, bBase, nBase);
}

// =======================================================================
// fc GEMM (+residual xc, cluster-fused norm), grid (64,4,1)
// =======================================================================
__global__ void __cluster_dims__(1,4,1) __launch_bounds__(256,2) hgemm_fc(
    const float* __restrict__ bfc, const float* __restrict__ x,
    float* __restrict__ out)
{
  const int tid = threadIdx.x;
  const int bBase = blockIdx.x * 128, nBase = blockIdx.y * 128;

  extern __shared__ char dsm[];
  const uint32_t dynU = (smem_u32(dsm) + 1023u) & ~1023u;
  __shared__ float biasS[128];
  __shared__ float redS[128][2];
  __shared__ float normP[128];
  __shared__ float scaleS[128];
  if (tid < 32) ((float4*)biasS)[tid] = ((const float4*)(bfc + nBase))[tid];

  float acc[2][8][4];
  #pragma unroll
  for (int m=0;m<2;m++) for (int n=0;n<8;n++) for (int i=0;i<4;i++) acc[m][n][i]=0.f;

  mainloop8(g_vh, Dd, g_wh + (size_t)34*WSZ, bBase, nBase, dynU, acc);

  norm_epilogue<true>(acc, biasS, redS, normP, scaleS,
                      out + 4096, XS, x + 4096, XS, bBase, nBase);
}

// =======================================================================
// mix: attn = q.kc; vh = fp16(l2norm(xc*attn + sum_w ap*xp_w + an*xn_w))
// =======================================================================
__global__ void mix_kernel(const float* __restrict__ x,
                           const float* __restrict__ dotP)
{
  __shared__ float sb[4];
  const int b = blockIdx.x, t = threadIdx.x;
  const __half* xhr = g_xh + (size_t)b*XS;

  uint2 qv = *(const uint2*)(g_qh + (size_t)b*Dd + t*4);
  uint2 kv = *(const uint2*)(g_qh + (size_t)(Bsz + b)*Dd + t*4);
  float2 qa = __half22float2(*(__half2*)&qv.x);
  float2 qb = __half22float2(*(__half2*)&qv.y);
  float2 ka = __half22float2(*(__half2*)&kv.x);
  float2 kb = __half22float2(*(__half2*)&kv.y);
  float part = qa.x*ka.x + qa.y*ka.y + qb.x*kb.x + qb.y*kb.y;
  #pragma unroll
  for (int o=16;o;o>>=1) part += __shfl_xor_sync(0xffffffffu, part, o);
  if ((t & 31) == 0) sb[t>>5] = part;
  __syncthreads();
  const float attn = sb[0] + sb[1] + sb[2] + sb[3];
  __syncthreads();

  float4 xc4 = ((const float4*)(x + (size_t)b*XS + 4096))[t];
  float4 acc;
  acc.x = xc4.x*attn; acc.y = xc4.y*attn; acc.z = xc4.z*attn; acc.w = xc4.w*attn;
  #pragma unroll
  for (int w=0;w<8;w++){
    float4 pa = *(const float4*)(dotP + ((size_t)w*Bsz + b)*4);
    float aw = pa.x + pa.y + pa.z + pa.w;
    uint2 up = *(const uint2*)(xhr + w*512 + t*4);
    float2 p0 = __half22float2(*(__half2*)&up.x);
    float2 p1 = __half22float2(*(__half2*)&up.y);
    acc.x += aw*p0.x; acc.y += aw*p0.y; acc.z += aw*p1.x; acc.w += aw*p1.y;
    float4 pn = *(const float4*)(dotP + ((size_t)(8+w)*Bsz + b)*4);
    float nw = pn.x + pn.y + pn.z + pn.w;
    uint2 un = *(const uint2*)(xhr + (9+w)*512 + t*4);
    float2 n0 = __half22float2(*(__half2*)&un.x);
    float2 n1 = __half22float2(*(__half2*)&un.y);
    acc.x += nw*n0.x; acc.y += nw*n0.y; acc.z += nw*n1.x; acc.w += nw*n1.y;
  }
  float ss = acc.x*acc.x + acc.y*acc.y + acc.z*acc.z + acc.w*acc.w;
  #pragma unroll
  for (int o=16;o;o>>=1) ss += __shfl_xor_sync(0xffffffffu, ss, o);
  if ((t & 31) == 0) sb[t>>5] = ss;
  __syncthreads();
  float tot = sb[0] + sb[1] + sb[2] + sb[3];
  float sc = 1.f / fmaxf(sqrtf(tot), 1e-12f);
  __half2 h0 = __floats2half2_rn(acc.x*sc, acc.y*sc);
  __half2 h1 = __floats2half2_rn(acc.z*sc, acc.w*sc);
  uint2 o; o.x = *(uint32_t*)&h0; o.y = *(uint32_t*)&h1;
  *(uint2*)(g_vh + (size_t)b*Dd + t*4) = o;
}

// =======================================================================
extern "C" void kernel_launch(void* const* d_in, const int* in_sizes, int n_in,
                              void* d_out, int out_size)
{
  const float* x   = (const float*)d_in[0];
  const float* Wq  = (const float*)d_in[1];
  const float* bq  = (const float*)d_in[2];
  const float* Wkc = (const float*)d_in[3];
  const float* bkc = (const float*)d_in[4];
  const float* Wkp = (const float*)d_in[5];
  const float* bkp = (const float*)d_in[6];
  const float* Wkn = (const float*)d_in[7];
  const float* bkn = (const float*)d_in[8];
  const float* Wfp = (const float*)d_in[9];
  const float* bfp = (const float*)d_in[10];
  const float* Wfn = (const float*)d_in[11];
  const float* bfn = (const float*)d_in[12];
  const float* Wfc = (const float*)d_in[13];
  const float* bfc = (const float*)d_in[14];
  float* out = (float*)d_out;

  float *dotP;
  cudaGetSymbolAddress((void**)&dotP, s_dotP);

  cudaFuncSetAttribute(hgemm_store, cudaFuncAttributeMaxDynamicSharedMemorySize, DYN_SMEM);
  cudaFuncSetAttribute(hgemm_dn,    cudaFuncAttributeMaxDynamicSharedMemorySize, DYN_SMEM);
  cudaFuncSetAttribute(hgemm_fc,    cudaFuncAttributeMaxDynamicSharedMemorySize, DYN_SMEM);

  // [0] x + all 35 weights -> fp16
  const int xBlocks = (Bsz*XS/8)/256;          // 34816
  const int wBlocks = (NW*(WSZ/8))/256;        // 4480
  cvtAll<<<xBlocks + wBlocks, 256>>>(x, Wq, Wkc, Wkp, Wkn, Wfp, Wfn, Wfc);

  // [1] q / kc (fp16 outputs)
  hgemm_store<<<dim3(64,4,2), 256, DYN_SMEM>>>(bq, bkc);

  // [2] paired DOT+NORM per window slot
  hgemm_dn<<<dim3(64,4,16), 256, DYN_SMEM>>>(bkp, bkn, bfp, bfn, dotP, out);

  // [3] mix -> vh (fp16 direct)
  mix_kernel<<<Bsz, 128>>>(x, dotP);

  // [4] fc (+ residual xc), cluster-fused norm
  hgemm_fc<<<dim3(64,4,1), 256, DYN_SMEM>>>(bfc, x, out);
}

// round 12
// speedup vs baseline: 1.1867x; 1.0081x over previous
#include <cuda_runtime.h>
#include <cuda_fp16.h>
#include <cstdint>

#define Bsz 8192
#define Dd  512
#define XS  8704           // 17*512 row stride of x / out
#define WSZ 262144         // 512*512 per weight matrix
#define NW  35
#define STG 32768          // per-stage smem: A 16K + B 16K
#define DYN_SMEM (3*STG + 1024)

// ---------------- device scratch (allocation-free rule) ----------------
__device__ __align__(256) __half g_xh[Bsz*XS];
__device__ __align__(256) __half g_wh[NW*WSZ];
__device__ __align__(256) __half g_vh[Bsz*Dd];
__device__ __align__(256) __half g_qh[2*Bsz*Dd];     // q then kc (fp16)
__device__ __align__(256) float  s_dotP[16*Bsz*4];   // [z][b][ctaN]

// ---------------- ptx helpers ----------------
__device__ __forceinline__ uint32_t smem_u32(const void* p){
  uint32_t a;
  asm("{ .reg .u64 t; cvta.to.shared.u64 t, %1; cvt.u32.u64 %0, t; }" : "=r"(a) : "l"(p));
  return a;
}
#define CP16(s,g) asm volatile("cp.async.cg.shared.global [%0], [%1], 16;" :: "r"(s), "l"(g))
#define CPCOMMIT() asm volatile("cp.async.commit_group;" ::: "memory")
#define CPWAIT1()  asm volatile("cp.async.wait_group 1;" ::: "memory")
#define CLUSTER_ARRIVE() asm volatile("barrier.cluster.arrive.aligned;" ::: "memory")
#define CLUSTER_WAIT()   asm volatile("barrier.cluster.wait.aligned;" ::: "memory")

__device__ __forceinline__ void ldsm4(uint32_t* r, uint32_t a){
  asm volatile("ldmatrix.sync.aligned.m8n8.x4.shared.b16 {%0,%1,%2,%3}, [%4];"
    : "=r"(r[0]),"=r"(r[1]),"=r"(r[2]),"=r"(r[3]) : "r"(a));
}
#define MMA(c,a,b0,b1) \
  asm volatile("mma.sync.aligned.m16n8k16.row.col.f32.f16.f16.f32 " \
    "{%0,%1,%2,%3},{%4,%5,%6,%7},{%8,%9},{%0,%1,%2,%3};" \
    : "+f"((c)[0]),"+f"((c)[1]),"+f"((c)[2]),"+f"((c)[3]) \
    : "r"((a)[0]),"r"((a)[1]),"r"((a)[2]),"r"((a)[3]),"r"(b0),"r"(b1))

#define SWZ(o) ((o) ^ (((o) >> 3) & 0x70))

// ---------------- fp32 -> fp16 conversion ----------------
__device__ __forceinline__ void cvt8core(const float* __restrict__ s, size_t i,
                                         __half* __restrict__ h){
  float4 a = ((const float4*)s)[2*i], b = ((const float4*)s)[2*i+1];
  __half2 H[4];
  H[0] = __half2(__float2half_rn(a.x), __float2half_rn(a.y));
  H[1] = __half2(__float2half_rn(a.z), __float2half_rn(a.w));
  H[2] = __half2(__float2half_rn(b.x), __float2half_rn(b.y));
  H[3] = __half2(__float2half_rn(b.z), __float2half_rn(b.w));
  ((uint4*)h)[i] = *(uint4*)H;
}

__global__ void cvtAll(const float* __restrict__ x,
                       const float* __restrict__ Wq,  const float* __restrict__ Wkc,
                       const float* __restrict__ Wkp, const float* __restrict__ Wkn,
                       const float* __restrict__ Wfp, const float* __restrict__ Wfn,
                       const float* __restrict__ Wfc){
  const int xB = (Bsz*XS/8)/256;
  const int bid = blockIdx.x;
  if (bid < xB){
    int i = bid*256 + threadIdx.x;
    cvt8core(x, i, g_xh);
  } else {
    int i = (bid - xB)*256 + threadIdx.x;
    int w = i >> 15;
    int j = i & 32767;
    const float* src;
    if      (w == 0)  src = Wq;
    else if (w == 1)  src = Wkc;
    else if (w < 10)  src = Wkp + (size_t)(w-2)*WSZ;
    else if (w < 18)  src = Wkn + (size_t)(w-10)*WSZ;
    else if (w < 26)  src = Wfp + (size_t)(w-18)*WSZ;
    else if (w < 34)  src = Wfn + (size_t)(w-26)*WSZ;
    else              src = Wfc;
    cvt8core(src, j, g_wh + (size_t)w*WSZ);
  }
}

// =======================================================================
// building blocks — 128-thread CTA, 4 warps, warp tile 64x64 (2M x 2N)
// =======================================================================
__device__ __forceinline__ void load_chunk(const __half* __restrict__ Ah, int lda,
                                           const __half* __restrict__ Wh,
                                           int bBase, int nBase, int kc,
                                           uint32_t base, int tid){
  const int kOff = kc * 64;
  #pragma unroll
  for (int i=0;i<8;i++){
    int idx = i*128 + tid, row = idx>>3, g = idx&7;
    uint32_t sw = SWZ((uint32_t)(row*128 + g*16));
    CP16(base + sw,         Ah + (size_t)(bBase+row)*(size_t)lda + kOff + g*8);
    CP16(base + 16384 + sw, Wh + (size_t)(nBase+row)*Dd + kOff + g*8);
  }
}

__device__ __forceinline__ void frag_setup(uint32_t (&aRowOff)[4], uint32_t (&bRowOff)[4],
                                           uint32_t (&selA)[4], uint32_t (&selB)[4]){
  const int tid = threadIdx.x, lane = tid & 31, wid = tid >> 5;
  const int warpM = wid >> 1, warpN = wid & 1;
  #pragma unroll
  for (int i=0;i<4;i++)
    aRowOff[i] = (uint32_t)((warpM*64 + i*16 + (lane&15)) * 128);
  #pragma unroll
  for (int i=0;i<4;i++)
    bRowOff[i] = (uint32_t)((warpN*64 + i*16 + (lane&7) + ((lane&16)>>1)) * 128);
  const int aXb = lane >> 4, bXb = (lane >> 3) & 1, lx = lane & 7;
  #pragma unroll
  for (int q=0;q<4;q++){
    selA[q] = (uint32_t)(((2*q + aXb) ^ lx) << 4);
    selB[q] = (uint32_t)(((2*q + bXb) ^ lx) << 4);
  }
}

// one k-chunk (k=64): 4 q-iters of k16, warp tile 64x64, reg double-buffered
__device__ __forceinline__ void compute_chunk(uint32_t aB, uint32_t bB,
    const uint32_t (&aRowOff)[4], const uint32_t (&bRowOff)[4],
    const uint32_t (&selA)[4], const uint32_t (&selB)[4],
    float (&acc)[4][8][4]){
  uint32_t aF[2][4][4], bF[2][2][4];
  #pragma unroll
  for (int m=0;m<4;m++) ldsm4(aF[0][m], aB + aRowOff[m] + selA[0]);
  ldsm4(bF[0][0], bB + bRowOff[0] + selB[0]);
  ldsm4(bF[0][1], bB + bRowOff[1] + selB[0]);
  #pragma unroll
  for (int q=0;q<4;q++){
    const int cur = q&1, nxt = cur^1;
    ldsm4(bF[1][0], bB + bRowOff[2] + selB[q]);
    ldsm4(bF[1][1], bB + bRowOff[3] + selB[q]);
    #pragma unroll
    for (int mt=0;mt<4;mt++)
      #pragma unroll
      for (int j=0;j<2;j++){
        MMA(acc[mt][j*2],   aF[cur][mt], bF[0][j][0], bF[0][j][1]);
        MMA(acc[mt][j*2+1], aF[cur][mt], bF[0][j][2], bF[0][j][3]);
      }
    if (q < 3){
      #pragma unroll
      for (int m=0;m<4;m++) ldsm4(aF[nxt][m], aB + aRowOff[m] + selA[q+1]);
      ldsm4(bF[0][0], bB + bRowOff[0] + selB[q+1]);
      ldsm4(bF[0][1], bB + bRowOff[1] + selB[q+1]);
    }
    #pragma unroll
    for (int mt=0;mt<4;mt++)
      #pragma unroll
      for (int j=0;j<2;j++){
        MMA(acc[mt][4+j*2],   aF[cur][mt], bF[1][j][0], bF[1][j][1]);
        MMA(acc[mt][4+j*2+1], aF[cur][mt], bF[1][j][2], bF[1][j][3]);
      }
  }
}

// non-persistent 8-chunk mainloop (store / fc kernels)
__device__ __forceinline__ void mainloop8(const __half* __restrict__ Ah, int lda,
                                          const __half* __restrict__ Wh,
                                          int bBase, int nBase, uint32_t dynU,
                                          float (&acc)[4][8][4]){
  const int tid = threadIdx.x;
  uint32_t aRowOff[4], bRowOff[4], selA[4], selB[4];
  frag_setup(aRowOff, bRowOff, selA, selB);
  load_chunk(Ah, lda, Wh, bBase, nBase, 0, dynU, tid);       CPCOMMIT();
  load_chunk(Ah, lda, Wh, bBase, nBase, 1, dynU + STG, tid); CPCOMMIT();
  #pragma unroll
  for (int s=0;s<8;s++){
    CPWAIT1();
    __syncthreads();
    if (s + 2 < 8) load_chunk(Ah, lda, Wh, bBase, nBase, s+2, dynU + ((s+2)%3)*STG, tid);
    CPCOMMIT();
    const uint32_t aB = dynU + (s%3)*STG;
    compute_chunk(aB, aB + 16384, aRowOff, bRowOff, selA, selB, acc);
  }
}

// NORM epilogue (cluster-fused l2 normalization over 4 N-CTAs)
template<bool RES>
__device__ __forceinline__ void norm_epilogue(
    float (&acc)[4][8][4], const float* biasS,
    float (*redS)[2], float* normP, float* scaleS,
    float* outPtr, int ldo, const float* R, int ldr,
    int bBase, int nBase)
{
  const int tid = threadIdx.x, lane = tid & 31, wid = tid >> 5;
  const int warpM = wid >> 1, warpN = wid & 1;
  #pragma unroll
  for (int mt=0;mt<4;mt++){
    const int rl0 = warpM*64 + mt*16 + (lane>>2);
    const float* r0p = RES ? (R + (size_t)(bBase+rl0)*(size_t)ldr) : nullptr;
    const float* r1p = RES ? (r0p + (size_t)8*(size_t)ldr) : nullptr;
    float s0 = 0.f, s1 = 0.f;
    #pragma unroll
    for (int nt=0;nt<8;nt++){
      const int bl = warpN*64 + nt*8 + ((lane&3)<<1);
      const int c  = nBase + bl;
      float bx = biasS[bl], by = biasS[bl+1];
      float v00 = acc[mt][nt][0]+bx, v01 = acc[mt][nt][1]+by;
      float v10 = acc[mt][nt][2]+bx, v11 = acc[mt][nt][3]+by;
      if (RES){
        float2 ra = *(const float2*)(r0p + c);
        float2 rb = *(const float2*)(r1p + c);
        v00 += ra.x; v01 += ra.y; v10 += rb.x; v11 += rb.y;
      }
      acc[mt][nt][0]=v00; acc[mt][nt][1]=v01;
      acc[mt][nt][2]=v10; acc[mt][nt][3]=v11;
      s0 += v00*v00 + v01*v01;
      s1 += v10*v10 + v11*v11;
    }
    s0 += __shfl_xor_sync(0xffffffffu, s0, 1); s0 += __shfl_xor_sync(0xffffffffu, s0, 2);
    s1 += __shfl_xor_sync(0xffffffffu, s1, 1); s1 += __shfl_xor_sync(0xffffffffu, s1, 2);
    if ((lane&3) == 0){ redS[rl0][warpN] = s0; redS[rl0+8][warpN] = s1; }
  }
  __syncthreads();
  normP[tid] = redS[tid][0] + redS[tid][1];
  CLUSTER_ARRIVE(); CLUSTER_WAIT();
  {
    const uint32_t loc = smem_u32(normP) + (uint32_t)tid*4;
    float tot = 0.f;
    #pragma unroll
    for (int r=0;r<4;r++){
      uint32_t rem; float pv;
      asm volatile("mapa.shared::cluster.u32 %0, %1, %2;" : "=r"(rem) : "r"(loc), "r"(r));
      asm volatile("ld.shared::cluster.f32 %0, [%1];" : "=f"(pv) : "r"(rem));
      tot += pv;
    }
    scaleS[tid] = 1.f / fmaxf(sqrtf(tot), 1e-12f);
  }
  CLUSTER_ARRIVE(); CLUSTER_WAIT();
  __syncthreads();
  #pragma unroll
  for (int mt=0;mt<4;mt++){
    const int rl0 = warpM*64 + mt*16 + (lane>>2);
    const float sc0 = scaleS[rl0], sc1 = scaleS[rl0+8];
    float* o0 = outPtr + (size_t)(bBase+rl0)*(size_t)ldo;
    float* o1 = o0 + (size_t)8*(size_t)ldo;
    #pragma unroll
    for (int nt=0;nt<8;nt++){
      const int c = nBase + warpN*64 + nt*8 + ((lane&3)<<1);
      *(float2*)(o0 + c) = make_float2(acc[mt][nt][0]*sc0, acc[mt][nt][1]*sc0);
      *(float2*)(o1 + c) = make_float2(acc[mt][nt][2]*sc1, acc[mt][nt][3]*sc1);
    }
  }
}

// =======================================================================
// q/kc GEMM -> fp16 output, grid (64,4,2), 128 threads
// =======================================================================
__global__ void __launch_bounds__(128,2) hgemm_store(
    const float* __restrict__ bq, const float* __restrict__ bkc)
{
  const int z = blockIdx.z;
  const __half* Ah = g_xh + 4096;
  const __half* Wh = g_wh + (size_t)z*WSZ;
  const float* bp = (z == 0) ? bq : bkc;
  __half* outPtr = g_qh + (size_t)z*Bsz*Dd;

  const int tid = threadIdx.x, lane = tid & 31, wid = tid >> 5;
  const int warpM = wid >> 1, warpN = wid & 1;
  const int bBase = blockIdx.x * 128, nBase = blockIdx.y * 128;

  extern __shared__ char dsm[];
  const uint32_t dynU = (smem_u32(dsm) + 1023u) & ~1023u;
  __shared__ float biasS[128];
  if (tid < 32) ((float4*)biasS)[tid] = ((const float4*)(bp + nBase))[tid];

  float acc[4][8][4];
  #pragma unroll
  for (int m=0;m<4;m++) for (int n=0;n<8;n++) for (int i=0;i<4;i++) acc[m][n][i]=0.f;

  mainloop8(Ah, XS, Wh, bBase, nBase, dynU, acc);

  #pragma unroll
  for (int mt=0;mt<4;mt++){
    const int rl0 = warpM*64 + mt*16 + (lane>>2);
    __half* o0 = outPtr + (size_t)(bBase+rl0)*Dd;
    __half* o1 = o0 + (size_t)8*Dd;
    #pragma unroll
    for (int nt=0;nt<8;nt++){
      const int bl = warpN*64 + nt*8 + ((lane&3)<<1);
      const int c  = nBase + bl;
      float bx = biasS[bl], by = biasS[bl+1];
      *(__half2*)(o0 + c) = __floats2half2_rn(acc[mt][nt][0]+bx, acc[mt][nt][1]+by);
      *(__half2*)(o1 + c) = __floats2half2_rn(acc[mt][nt][2]+bx, acc[mt][nt][3]+by);
    }
  }
}

// =======================================================================
// paired DOT+NORM kernel: grid (64,4,16), cluster (1,4,1), 128 threads.
// chunks 0-7 with Wk (-> DOT epilogue), chunks 8-15 with Wf (-> NORM).
// =======================================================================
__global__ void __cluster_dims__(1,4,1) __launch_bounds__(128,2) hgemm_dn(
    const float* __restrict__ bkp, const float* __restrict__ bkn,
    const float* __restrict__ bfp, const float* __restrict__ bfn,
    float* __restrict__ dotP, float* __restrict__ out)
{
  const int zw = blockIdx.z;                       // 0..15 window slot
  const int widx = zw + (zw >= 8 ? 1 : 0);         // skip center
  const __half* Ah = g_xh + widx*Dd;
  const __half* Wk = g_wh + (size_t)(2  + zw)*WSZ;
  const __half* Wf = g_wh + (size_t)(18 + zw)*WSZ;
  const float* bpK = (zw < 8) ? bkp + (size_t)zw*Dd : bkn + (size_t)(zw-8)*Dd;
  const float* bpF = (zw < 8) ? bfp + (size_t)zw*Dd : bfn + (size_t)(zw-8)*Dd;

  const int tid = threadIdx.x, lane = tid & 31, wid = tid >> 5;
  const int warpM = wid >> 1, warpN = wid & 1;
  const int bBase = blockIdx.x * 128, nBase = blockIdx.y * 128;

  extern __shared__ char dsm[];
  const uint32_t dynU = (smem_u32(dsm) + 1023u) & ~1023u;
  __shared__ float biasK[128];
  __shared__ float biasF[128];
  __shared__ float redS[128][2];
  __shared__ float normP[128];
  __shared__ float scaleS[128];
  if (tid < 32){
    ((float4*)biasK)[tid] = ((const float4*)(bpK + nBase))[tid];
    ((float4*)biasF)[tid] = ((const float4*)(bpF + nBase))[tid];
  }

  uint32_t aRowOff[4], bRowOff[4], selA[4], selB[4];
  frag_setup(aRowOff, bRowOff, selA, selB);

  float acc[4][8][4];
  #pragma unroll
  for (int m=0;m<4;m++) for (int n=0;n<8;n++) for (int i=0;i<4;i++) acc[m][n][i]=0.f;

  // continuous 16-chunk pipeline (chunk c: kc=c&7, W = c<8 ? Wk : Wf)
  load_chunk(Ah, XS, Wk, bBase, nBase, 0, dynU,       tid); CPCOMMIT();
  load_chunk(Ah, XS, Wk, bBase, nBase, 1, dynU + STG, tid); CPCOMMIT();

  #pragma unroll
  for (int c = 0; c < 16; c++){
    CPWAIT1();
    __syncthreads();
    if (c + 2 < 16){
      const int lc = c + 2;
      load_chunk(Ah, XS, (lc < 8) ? Wk : Wf, bBase, nBase, lc & 7,
                 dynU + (uint32_t)(lc % 3)*STG, tid);
    }
    CPCOMMIT();
    const uint32_t aB = dynU + (uint32_t)(c % 3)*STG;
    compute_chunk(aB, aB + 16384, aRowOff, bRowOff, selA, selB, acc);

    if (c == 7){
      // ---- DOT epilogue (hidden behind in-flight chunk 8/9 loads) ----
      #pragma unroll
      for (int mt=0;mt<4;mt++){
        const int rl0 = warpM*64 + mt*16 + (lane>>2);
        const __half* q0 = g_qh + (size_t)(bBase+rl0)*Dd;
        const __half* q1 = q0 + (size_t)8*Dd;
        float s0 = 0.f, s1 = 0.f;
        #pragma unroll
        for (int nt=0;nt<8;nt++){
          const int bl = warpN*64 + nt*8 + ((lane&3)<<1);
          const int cc = nBase + bl;
          float bx = biasK[bl], by = biasK[bl+1];
          float2 qa = __half22float2(*(const __half2*)(q0 + cc));
          float2 qb = __half22float2(*(const __half2*)(q1 + cc));
          s0 += (acc[mt][nt][0]+bx)*qa.x + (acc[mt][nt][1]+by)*qa.y;
          s1 += (acc[mt][nt][2]+bx)*qb.x + (acc[mt][nt][3]+by)*qb.y;
        }
        s0 += __shfl_xor_sync(0xffffffffu, s0, 1); s0 += __shfl_xor_sync(0xffffffffu, s0, 2);
        s1 += __shfl_xor_sync(0xffffffffu, s1, 1); s1 += __shfl_xor_sync(0xffffffffu, s1, 2);
        if ((lane&3) == 0){ redS[rl0][warpN] = s0; redS[rl0+8][warpN] = s1; }
      }
      __syncthreads();
      {
        float p = redS[tid][0] + redS[tid][1];
        dotP[((size_t)zw*Bsz + bBase + tid)*4 + blockIdx.y] = p;
      }
      // reset accumulators for the NORM GEMM
      #pragma unroll
      for (int m=0;m<4;m++) for (int n=0;n<8;n++) for (int i=0;i<4;i++) acc[m][n][i]=0.f;
    }
  }

  norm_epilogue<false>(acc, biasF, redS, normP, scaleS,
                       out + (size_t)widx*Dd, XS, nullptr, 0, bBase, nBase);
}

// =======================================================================
// fc GEMM (+residual xc, cluster-fused norm), grid (64,4,1), 128 threads
// =======================================================================
__global__ void __cluster_dims__(1,4,1) __launch_bounds__(128,2) hgemm_fc(
    const float* __restrict__ bfc, const float* __restrict__ x,
    float* __restrict__ out)
{
  const int tid = threadIdx.x;
  const int bBase = blockIdx.x * 128, nBase = blockIdx.y * 128;

  extern __shared__ char dsm[];
  const uint32_t dynU = (smem_u32(dsm) + 1023u) & ~1023u;
  __shared__ float biasS[128];
  __shared__ float redS[128][2];
  __shared__ float normP[128];
  __shared__ float scaleS[128];
  if (tid < 32) ((float4*)biasS)[tid] = ((const float4*)(bfc + nBase))[tid];

  float acc[4][8][4];
  #pragma unroll
  for (int m=0;m<4;m++) for (int n=0;n<8;n++) for (int i=0;i<4;i++) acc[m][n][i]=0.f;

  mainloop8(g_vh, Dd, g_wh + (size_t)34*WSZ, bBase, nBase, dynU, acc);

  norm_epilogue<true>(acc, biasS, redS, normP, scaleS,
                      out + 4096, XS, x + 4096, XS, bBase, nBase);
}

// =======================================================================
// mix: attn = q.kc; vh = fp16(l2norm(xc*attn + sum_w ap*xp_w + an*xn_w))
// =======================================================================
__global__ void mix_kernel(const float* __restrict__ x,
                           const float* __restrict__ dotP)
{
  __shared__ float sb[4];
  const int b = blockIdx.x, t = threadIdx.x;
  const __half* xhr = g_xh + (size_t)b*XS;

  uint2 qv = *(const uint2*)(g_qh + (size_t)b*Dd + t*4);
  uint2 kv = *(const uint2*)(g_qh + (size_t)(Bsz + b)*Dd + t*4);
  float2 qa = __half22float2(*(__half2*)&qv.x);
  float2 qb = __half22float2(*(__half2*)&qv.y);
  float2 ka = __half22float2(*(__half2*)&kv.x);
  float2 kb = __half22float2(*(__half2*)&kv.y);
  float part = qa.x*ka.x + qa.y*ka.y + qb.x*kb.x + qb.y*kb.y;
  #pragma unroll
  for (int o=16;o;o>>=1) part += __shfl_xor_sync(0xffffffffu, part, o);
  if ((t & 31) == 0) sb[t>>5] = part;
  __syncthreads();
  const float attn = sb[0] + sb[1] + sb[2] + sb[3];
  __syncthreads();

  float4 xc4 = ((const float4*)(x + (size_t)b*XS + 4096))[t];
  float4 acc;
  acc.x = xc4.x*attn; acc.y = xc4.y*attn; acc.z = xc4.z*attn; acc.w = xc4.w*attn;
  #pragma unroll
  for (int w=0;w<8;w++){
    float4 pa = *(const float4*)(dotP + ((size_t)w*Bsz + b)*4);
    float aw = pa.x + pa.y + pa.z + pa.w;
    uint2 up = *(const uint2*)(xhr + w*512 + t*4);
    float2 p0 = __half22float2(*(__half2*)&up.x);
    float2 p1 = __half22float2(*(__half2*)&up.y);
    acc.x += aw*p0.x; acc.y += aw*p0.y; acc.z += aw*p1.x; acc.w += aw*p1.y;
    float4 pn = *(const float4*)(dotP + ((size_t)(8+w)*Bsz + b)*4);
    float nw = pn.x + pn.y + pn.z + pn.w;
    uint2 un = *(const uint2*)(xhr + (9+w)*512 + t*4);
    float2 n0 = __half22float2(*(__half2*)&un.x);
    float2 n1 = __half22float2(*(__half2*)&un.y);
    acc.x += nw*n0.x; acc.y += nw*n0.y; acc.z += nw*n1.x; acc.w += nw*n1.y;
  }
  float ss = acc.x*acc.x + acc.y*acc.y + acc.z*acc.z + acc.w*acc.w;
  #pragma unroll
  for (int o=16;o;o>>=1) ss += __shfl_xor_sync(0xffffffffu, ss, o);
  if ((t & 31) == 0) sb[t>>5] = ss;
  __syncthreads();
  float tot = sb[0] + sb[1] + sb[2] + sb[3];
  float sc = 1.f / fmaxf(sqrtf(tot), 1e-12f);
  __half2 h0 = __floats2half2_rn(acc.x*sc, acc.y*sc);
  __half2 h1 = __floats2half2_rn(acc.z*sc, acc.w*sc);
  uint2 o; o.x = *(uint32_t*)&h0; o.y = *(uint32_t*)&h1;
  *(uint2*)(g_vh + (size_t)b*Dd + t*4) = o;
}

// =======================================================================
extern "C" void kernel_launch(void* const* d_in, const int* in_sizes, int n_in,
                              void* d_out, int out_size)
{
  const float* x   = (const float*)d_in[0];
  const float* Wq  = (const float*)d_in[1];
  const float* bq  = (const float*)d_in[2];
  const float* Wkc = (const float*)d_in[3];
  const float* bkc = (const float*)d_in[4];
  const float* Wkp = (const float*)d_in[5];
  const float* bkp = (const float*)d_in[6];
  const float* Wkn = (const float*)d_in[7];
  const float* bkn = (const float*)d_in[8];
  const float* Wfp = (const float*)d_in[9];
  const float* bfp = (const float*)d_in[10];
  const float* Wfn = (const float*)d_in[11];
  const float* bfn = (const float*)d_in[12];
  const float* Wfc = (const float*)d_in[13];
  const float* bfc = (const float*)d_in[14];
  float* out = (float*)d_out;

  float *dotP;
  cudaGetSymbolAddress((void**)&dotP, s_dotP);

  cudaFuncSetAttribute(hgemm_store, cudaFuncAttributeMaxDynamicSharedMemorySize, DYN_SMEM);
  cudaFuncSetAttribute(hgemm_dn,    cudaFuncAttributeMaxDynamicSharedMemorySize, DYN_SMEM);
  cudaFuncSetAttribute(hgemm_fc,    cudaFuncAttributeMaxDynamicSharedMemorySize, DYN_SMEM);

  // [0] x + all 35 weights -> fp16
  const int xBlocks = (Bsz*XS/8)/256;          // 34816
  const int wBlocks = (NW*(WSZ/8))/256;        // 4480
  cvtAll<<<xBlocks + wBlocks, 256>>>(x, Wq, Wkc, Wkp, Wkn, Wfp, Wfn, Wfc);

  // [1] q / kc (fp16 outputs)
  hgemm_store<<<dim3(64,4,2), 128, DYN_SMEM>>>(bq, bkc);

  // [2] paired DOT+NORM per window slot
  hgemm_dn<<<dim3(64,4,16), 128, DYN_SMEM>>>(bkp, bkn, bfp, bfn, dotP, out);

  // [3] mix -> vh (fp16 direct)
  mix_kernel<<<Bsz, 128>>>(x, dotP);

  // [4] fc (+ residual xc), cluster-fused norm
  hgemm_fc<<<dim3(64,4,1), 128, DYN_SMEM>>>(bfc, x, out);
}

// round 13
// speedup vs baseline: 1.1868x; 1.0001x over previous
#include <cuda_runtime.h>
#include <cuda_fp16.h>
#include <cstdint>

#define Bsz 8192
#define Dd  512
#define XS  8704           // 17*512 row stride of x / out
#define WSZ 262144         // 512*512 per weight matrix
#define NW  35
#define STG 32768          // per-stage smem: A 16K + B 16K
#define DYN_SMEM (3*STG + 1024)

// ---------------- device scratch (allocation-free rule) ----------------
__device__ __align__(256) __half g_xh[Bsz*XS];
__device__ __align__(256) __half g_wh[NW*WSZ];
__device__ __align__(256) __half g_vh[Bsz*Dd];
__device__ __align__(256) __half g_qh[2*Bsz*Dd];     // q then kc (fp16)
__device__ __align__(256) float  s_dotP[16*Bsz*4];   // [z][b][ctaN]

// ---------------- ptx helpers ----------------
__device__ __forceinline__ uint32_t smem_u32(const void* p){
  uint32_t a;
  asm("{ .reg .u64 t; cvta.to.shared.u64 t, %1; cvt.u32.u64 %0, t; }" : "=r"(a) : "l"(p));
  return a;
}
#define CP16(s,g) asm volatile("cp.async.cg.shared.global [%0], [%1], 16;" :: "r"(s), "l"(g))
#define CPCOMMIT() asm volatile("cp.async.commit_group;" ::: "memory")
#define CPWAIT1()  asm volatile("cp.async.wait_group 1;" ::: "memory")
#define CLUSTER_ARRIVE() asm volatile("barrier.cluster.arrive.aligned;" ::: "memory")
#define CLUSTER_WAIT()   asm volatile("barrier.cluster.wait.aligned;" ::: "memory")

__device__ __forceinline__ void ldsm4(uint32_t* r, uint32_t a){
  asm volatile("ldmatrix.sync.aligned.m8n8.x4.shared.b16 {%0,%1,%2,%3}, [%4];"
    : "=r"(r[0]),"=r"(r[1]),"=r"(r[2]),"=r"(r[3]) : "r"(a));
}
#define MMA(c,a,b0,b1) \
  asm volatile("mma.sync.aligned.m16n8k16.row.col.f32.f16.f16.f32 " \
    "{%0,%1,%2,%3},{%4,%5,%6,%7},{%8,%9},{%0,%1,%2,%3};" \
    : "+f"((c)[0]),"+f"((c)[1]),"+f"((c)[2]),"+f"((c)[3]) \
    : "r"((a)[0]),"r"((a)[1]),"r"((a)[2]),"r"((a)[3]),"r"(b0),"r"(b1))

#define SWZ(o) ((o) ^ (((o) >> 3) & 0x70))

// ---------------- fp32 -> fp16 conversion ----------------
__device__ __forceinline__ void cvt8core(const float* __restrict__ s, size_t i,
                                         __half* __restrict__ h){
  float4 a = ((const float4*)s)[2*i], b = ((const float4*)s)[2*i+1];
  __half2 H[4];
  H[0] = __half2(__float2half_rn(a.x), __float2half_rn(a.y));
  H[1] = __half2(__float2half_rn(a.z), __float2half_rn(a.w));
  H[2] = __half2(__float2half_rn(b.x), __float2half_rn(b.y));
  H[3] = __half2(__float2half_rn(b.z), __float2half_rn(b.w));
  ((uint4*)h)[i] = *(uint4*)H;
}

// x + Wq + Wkc (everything hgemm_store needs)
__global__ void cvtPre(const float* __restrict__ x,
                       const float* __restrict__ Wq, const float* __restrict__ Wkc){
  const int xB = (Bsz*XS/8)/256;   // 34816
  const int bid = blockIdx.x;
  if (bid < xB){
    int i = bid*256 + threadIdx.x;
    cvt8core(x, i, g_xh);
  } else {
    int i = (bid - xB)*256 + threadIdx.x;
    int w = i >> 15, j = i & 32767;
    const float* src = (w == 0) ? Wq : Wkc;
    cvt8core(src, j, g_wh + (size_t)w*WSZ);
  }
}

// W2..W34 (33 matrices) — runs on a side stream, overlapped with hgemm_store
__global__ void cvtWrest(const float* __restrict__ Wkp, const float* __restrict__ Wkn,
                         const float* __restrict__ Wfp, const float* __restrict__ Wfn,
                         const float* __restrict__ Wfc){
  int i = blockIdx.x*256 + threadIdx.x;
  int w = (i >> 15) + 2;           // 2..34
  int j = i & 32767;
  const float* src;
  if      (w < 10)  src = Wkp + (size_t)(w-2)*WSZ;
  else if (w < 18)  src = Wkn + (size_t)(w-10)*WSZ;
  else if (w < 26)  src = Wfp + (size_t)(w-18)*WSZ;
  else if (w < 34)  src = Wfn + (size_t)(w-26)*WSZ;
  else              src = Wfc;
  cvt8core(src, j, g_wh + (size_t)w*WSZ);
}

// =======================================================================
// building blocks — 128-thread CTA, 4 warps, warp tile 64x64 (2M x 2N)
// =======================================================================
__device__ __forceinline__ void load_chunk(const __half* __restrict__ Ah, int lda,
                                           const __half* __restrict__ Wh,
                                           int bBase, int nBase, int kc,
                                           uint32_t base, int tid){
  const int kOff = kc * 64;
  #pragma unroll
  for (int i=0;i<8;i++){
    int idx = i*128 + tid, row = idx>>3, g = idx&7;
    uint32_t sw = SWZ((uint32_t)(row*128 + g*16));
    CP16(base + sw,         Ah + (size_t)(bBase+row)*(size_t)lda + kOff + g*8);
    CP16(base + 16384 + sw, Wh + (size_t)(nBase+row)*Dd + kOff + g*8);
  }
}

__device__ __forceinline__ void frag_setup(uint32_t (&aRowOff)[4], uint32_t (&bRowOff)[4],
                                           uint32_t (&selA)[4], uint32_t (&selB)[4]){
  const int tid = threadIdx.x, lane = tid & 31, wid = tid >> 5;
  const int warpM = wid >> 1, warpN = wid & 1;
  #pragma unroll
  for (int i=0;i<4;i++)
    aRowOff[i] = (uint32_t)((warpM*64 + i*16 + (lane&15)) * 128);
  #pragma unroll
  for (int i=0;i<4;i++)
    bRowOff[i] = (uint32_t)((warpN*64 + i*16 + (lane&7) + ((lane&16)>>1)) * 128);
  const int aXb = lane >> 4, bXb = (lane >> 3) & 1, lx = lane & 7;
  #pragma unroll
  for (int q=0;q<4;q++){
    selA[q] = (uint32_t)(((2*q + aXb) ^ lx) << 4);
    selB[q] = (uint32_t)(((2*q + bXb) ^ lx) << 4);
  }
}

__device__ __forceinline__ void compute_chunk(uint32_t aB, uint32_t bB,
    const uint32_t (&aRowOff)[4], const uint32_t (&bRowOff)[4],
    const uint32_t (&selA)[4], const uint32_t (&selB)[4],
    float (&acc)[4][8][4]){
  uint32_t aF[2][4][4], bF[2][2][4];
  #pragma unroll
  for (int m=0;m<4;m++) ldsm4(aF[0][m], aB + aRowOff[m] + selA[0]);
  ldsm4(bF[0][0], bB + bRowOff[0] + selB[0]);
  ldsm4(bF[0][1], bB + bRowOff[1] + selB[0]);
  #pragma unroll
  for (int q=0;q<4;q++){
    const int cur = q&1, nxt = cur^1;
    ldsm4(bF[1][0], bB + bRowOff[2] + selB[q]);
    ldsm4(bF[1][1], bB + bRowOff[3] + selB[q]);
    #pragma unroll
    for (int mt=0;mt<4;mt++)
      #pragma unroll
      for (int j=0;j<2;j++){
        MMA(acc[mt][j*2],   aF[cur][mt], bF[0][j][0], bF[0][j][1]);
        MMA(acc[mt][j*2+1], aF[cur][mt], bF[0][j][2], bF[0][j][3]);
      }
    if (q < 3){
      #pragma unroll
      for (int m=0;m<4;m++) ldsm4(aF[nxt][m], aB + aRowOff[m] + selA[q+1]);
      ldsm4(bF[0][0], bB + bRowOff[0] + selB[q+1]);
      ldsm4(bF[0][1], bB + bRowOff[1] + selB[q+1]);
    }
    #pragma unroll
    for (int mt=0;mt<4;mt++)
      #pragma unroll
      for (int j=0;j<2;j++){
        MMA(acc[mt][4+j*2],   aF[cur][mt], bF[1][j][0], bF[1][j][1]);
        MMA(acc[mt][4+j*2+1], aF[cur][mt], bF[1][j][2], bF[1][j][3]);
      }
  }
}

__device__ __forceinline__ void mainloop8(const __half* __restrict__ Ah, int lda,
                                          const __half* __restrict__ Wh,
                                          int bBase, int nBase, uint32_t dynU,
                                          float (&acc)[4][8][4]){
  const int tid = threadIdx.x;
  uint32_t aRowOff[4], bRowOff[4], selA[4], selB[4];
  frag_setup(aRowOff, bRowOff, selA, selB);
  load_chunk(Ah, lda, Wh, bBase, nBase, 0, dynU, tid);       CPCOMMIT();
  load_chunk(Ah, lda, Wh, bBase, nBase, 1, dynU + STG, tid); CPCOMMIT();
  #pragma unroll
  for (int s=0;s<8;s++){
    CPWAIT1();
    __syncthreads();
    if (s + 2 < 8) load_chunk(Ah, lda, Wh, bBase, nBase, s+2, dynU + ((s+2)%3)*STG, tid);
    CPCOMMIT();
    const uint32_t aB = dynU + (s%3)*STG;
    compute_chunk(aB, aB + 16384, aRowOff, bRowOff, selA, selB, acc);
  }
}

// NORM epilogue (cluster-fused l2 normalization over 4 N-CTAs)
template<bool RES>
__device__ __forceinline__ void norm_epilogue(
    float (&acc)[4][8][4], const float* biasS,
    float (*redS)[2], float* normP, float* scaleS,
    float* outPtr, int ldo, const float* R, int ldr,
    int bBase, int nBase)
{
  const int tid = threadIdx.x, lane = tid & 31, wid = tid >> 5;
  const int warpM = wid >> 1, warpN = wid & 1;
  #pragma unroll
  for (int mt=0;mt<4;mt++){
    const int rl0 = warpM*64 + mt*16 + (lane>>2);
    const float* r0p = RES ? (R + (size_t)(bBase+rl0)*(size_t)ldr) : nullptr;
    const float* r1p = RES ? (r0p + (size_t)8*(size_t)ldr) : nullptr;
    float s0 = 0.f, s1 = 0.f;
    #pragma unroll
    for (int nt=0;nt<8;nt++){
      const int bl = warpN*64 + nt*8 + ((lane&3)<<1);
      const int c  = nBase + bl;
      float bx = biasS[bl], by = biasS[bl+1];
      float v00 = acc[mt][nt][0]+bx, v01 = acc[mt][nt][1]+by;
      float v10 = acc[mt][nt][2]+bx, v11 = acc[mt][nt][3]+by;
      if (RES){
        float2 ra = *(const float2*)(r0p + c);
        float2 rb = *(const float2*)(r1p + c);
        v00 += ra.x; v01 += ra.y; v10 += rb.x; v11 += rb.y;
      }
      acc[mt][nt][0]=v00; acc[mt][nt][1]=v01;
      acc[mt][nt][2]=v10; acc[mt][nt][3]=v11;
      s0 += v00*v00 + v01*v01;
      s1 += v10*v10 + v11*v11;
    }
    s0 += __shfl_xor_sync(0xffffffffu, s0, 1); s0 += __shfl_xor_sync(0xffffffffu, s0, 2);
    s1 += __shfl_xor_sync(0xffffffffu, s1, 1); s1 += __shfl_xor_sync(0xffffffffu, s1, 2);
    if ((lane&3) == 0){ redS[rl0][warpN] = s0; redS[rl0+8][warpN] = s1; }
  }
  __syncthreads();
  normP[tid] = redS[tid][0] + redS[tid][1];
  CLUSTER_ARRIVE(); CLUSTER_WAIT();
  {
    const uint32_t loc = smem_u32(normP) + (uint32_t)tid*4;
    float tot = 0.f;
    #pragma unroll
    for (int r=0;r<4;r++){
      uint32_t rem; float pv;
      asm volatile("mapa.shared::cluster.u32 %0, %1, %2;" : "=r"(rem) : "r"(loc), "r"(r));
      asm volatile("ld.shared::cluster.f32 %0, [%1];" : "=f"(pv) : "r"(rem));
      tot += pv;
    }
    scaleS[tid] = 1.f / fmaxf(sqrtf(tot), 1e-12f);
  }
  CLUSTER_ARRIVE(); CLUSTER_WAIT();
  __syncthreads();
  #pragma unroll
  for (int mt=0;mt<4;mt++){
    const int rl0 = warpM*64 + mt*16 + (lane>>2);
    const float sc0 = scaleS[rl0], sc1 = scaleS[rl0+8];
    float* o0 = outPtr + (size_t)(bBase+rl0)*(size_t)ldo;
    float* o1 = o0 + (size_t)8*(size_t)ldo;
    #pragma unroll
    for (int nt=0;nt<8;nt++){
      const int c = nBase + warpN*64 + nt*8 + ((lane&3)<<1);
      *(float2*)(o0 + c) = make_float2(acc[mt][nt][0]*sc0, acc[mt][nt][1]*sc0);
      *(float2*)(o1 + c) = make_float2(acc[mt][nt][2]*sc1, acc[mt][nt][3]*sc1);
    }
  }
}

// =======================================================================
// q/kc GEMM -> fp16 output, grid (64,4,2), 128 threads
// =======================================================================
__global__ void __launch_bounds__(128,2) hgemm_store(
    const float* __restrict__ bq, const float* __restrict__ bkc)
{
  const int z = blockIdx.z;
  const __half* Ah = g_xh + 4096;
  const __half* Wh = g_wh + (size_t)z*WSZ;
  const float* bp = (z == 0) ? bq : bkc;
  __half* outPtr = g_qh + (size_t)z*Bsz*Dd;

  const int tid = threadIdx.x, lane = tid & 31, wid = tid >> 5;
  const int warpM = wid >> 1, warpN = wid & 1;
  const int bBase = blockIdx.x * 128, nBase = blockIdx.y * 128;

  extern __shared__ char dsm[];
  const uint32_t dynU = (smem_u32(dsm) + 1023u) & ~1023u;
  __shared__ float biasS[128];
  if (tid < 32) ((float4*)biasS)[tid] = ((const float4*)(bp + nBase))[tid];

  float acc[4][8][4];
  #pragma unroll
  for (int m=0;m<4;m++) for (int n=0;n<8;n++) for (int i=0;i<4;i++) acc[m][n][i]=0.f;

  mainloop8(Ah, XS, Wh, bBase, nBase, dynU, acc);

  #pragma unroll
  for (int mt=0;mt<4;mt++){
    const int rl0 = warpM*64 + mt*16 + (lane>>2);
    __half* o0 = outPtr + (size_t)(bBase+rl0)*Dd;
    __half* o1 = o0 + (size_t)8*Dd;
    #pragma unroll
    for (int nt=0;nt<8;nt++){
      const int bl = warpN*64 + nt*8 + ((lane&3)<<1);
      const int c  = nBase + bl;
      float bx = biasS[bl], by = biasS[bl+1];
      *(__half2*)(o0 + c) = __floats2half2_rn(acc[mt][nt][0]+bx, acc[mt][nt][1]+by);
      *(__half2*)(o1 + c) = __floats2half2_rn(acc[mt][nt][2]+bx, acc[mt][nt][3]+by);
    }
  }
}

// =======================================================================
// paired DOT+NORM kernel: grid (64,4,16), cluster (1,4,1), 128 threads.
// =======================================================================
__global__ void __cluster_dims__(1,4,1) __launch_bounds__(128,2) hgemm_dn(
    const float* __restrict__ bkp, const float* __restrict__ bkn,
    const float* __restrict__ bfp, const float* __restrict__ bfn,
    float* __restrict__ dotP, float* __restrict__ out)
{
  const int zw = blockIdx.z;                       // 0..15 window slot
  const int widx = zw + (zw >= 8 ? 1 : 0);         // skip center
  const __half* Ah = g_xh + widx*Dd;
  const __half* Wk = g_wh + (size_t)(2  + zw)*WSZ;
  const __half* Wf = g_wh + (size_t)(18 + zw)*WSZ;
  const float* bpK = (zw < 8) ? bkp + (size_t)zw*Dd : bkn + (size_t)(zw-8)*Dd;
  const float* bpF = (zw < 8) ? bfp + (size_t)zw*Dd : bfn + (size_t)(zw-8)*Dd;

  const int tid = threadIdx.x, lane = tid & 31, wid = tid >> 5;
  const int warpM = wid >> 1, warpN = wid & 1;
  const int bBase = blockIdx.x * 128, nBase = blockIdx.y * 128;

  extern __shared__ char dsm[];
  const uint32_t dynU = (smem_u32(dsm) + 1023u) & ~1023u;
  __shared__ float biasK[128];
  __shared__ float biasF[128];
  __shared__ float redS[128][2];
  __shared__ float normP[128];
  __shared__ float scaleS[128];
  if (tid < 32){
    ((float4*)biasK)[tid] = ((const float4*)(bpK + nBase))[tid];
    ((float4*)biasF)[tid] = ((const float4*)(bpF + nBase))[tid];
  }

  uint32_t aRowOff[4], bRowOff[4], selA[4], selB[4];
  frag_setup(aRowOff, bRowOff, selA, selB);

  float acc[4][8][4];
  #pragma unroll
  for (int m=0;m<4;m++) for (int n=0;n<8;n++) for (int i=0;i<4;i++) acc[m][n][i]=0.f;

  load_chunk(Ah, XS, Wk, bBase, nBase, 0, dynU,       tid); CPCOMMIT();
  load_chunk(Ah, XS, Wk, bBase, nBase, 1, dynU + STG, tid); CPCOMMIT();

  #pragma unroll
  for (int c = 0; c < 16; c++){
    CPWAIT1();
    __syncthreads();
    if (c + 2 < 16){
      const int lc = c + 2;
      load_chunk(Ah, XS, (lc < 8) ? Wk : Wf, bBase, nBase, lc & 7,
                 dynU + (uint32_t)(lc % 3)*STG, tid);
    }
    CPCOMMIT();
    const uint32_t aB = dynU + (uint32_t)(c % 3)*STG;
    compute_chunk(aB, aB + 16384, aRowOff, bRowOff, selA, selB, acc);

    if (c == 7){
      // ---- DOT epilogue (hidden behind in-flight chunk 8/9 loads) ----
      #pragma unroll
      for (int mt=0;mt<4;mt++){
        const int rl0 = warpM*64 + mt*16 + (lane>>2);
        const __half* q0 = g_qh + (size_t)(bBase+rl0)*Dd;
        const __half* q1 = q0 + (size_t)8*Dd;
        float s0 = 0.f, s1 = 0.f;
        #pragma unroll
        for (int nt=0;nt<8;nt++){
          const int bl = warpN*64 + nt*8 + ((lane&3)<<1);
          const int cc = nBase + bl;
          float bx = biasK[bl], by = biasK[bl+1];
          float2 qa = __half22float2(*(const __half2*)(q0 + cc));
          float2 qb = __half22float2(*(const __half2*)(q1 + cc));
          s0 += (acc[mt][nt][0]+bx)*qa.x + (acc[mt][nt][1]+by)*qa.y;
          s1 += (acc[mt][nt][2]+bx)*qb.x + (acc[mt][nt][3]+by)*qb.y;
        }
        s0 += __shfl_xor_sync(0xffffffffu, s0, 1); s0 += __shfl_xor_sync(0xffffffffu, s0, 2);
        s1 += __shfl_xor_sync(0xffffffffu, s1, 1); s1 += __shfl_xor_sync(0xffffffffu, s1, 2);
        if ((lane&3) == 0){ redS[rl0][warpN] = s0; redS[rl0+8][warpN] = s1; }
      }
      __syncthreads();
      {
        float p = redS[tid][0] + redS[tid][1];
        dotP[((size_t)zw*Bsz + bBase + tid)*4 + blockIdx.y] = p;
      }
      #pragma unroll
      for (int m=0;m<4;m++) for (int n=0;n<8;n++) for (int i=0;i<4;i++) acc[m][n][i]=0.f;
    }
  }

  norm_epilogue<false>(acc, biasF, redS, normP, scaleS,
                       out + (size_t)widx*Dd, XS, nullptr, 0, bBase, nBase);
}

// =======================================================================
// fc GEMM (+residual xc, cluster-fused norm), grid (64,4,1), 128 threads
// =======================================================================
__global__ void __cluster_dims__(1,4,1) __launch_bounds__(128,2) hgemm_fc(
    const float* __restrict__ bfc, const float* __restrict__ x,
    float* __restrict__ out)
{
  const int tid = threadIdx.x;
  const int bBase = blockIdx.x * 128, nBase = blockIdx.y * 128;

  extern __shared__ char dsm[];
  const uint32_t dynU = (smem_u32(dsm) + 1023u) & ~1023u;
  __shared__ float biasS[128];
  __shared__ float redS[128][2];
  __shared__ float normP[128];
  __shared__ float scaleS[128];
  if (tid < 32) ((float4*)biasS)[tid] = ((const float4*)(bfc + nBase))[tid];

  float acc[4][8][4];
  #pragma unroll
  for (int m=0;m<4;m++) for (int n=0;n<8;n++) for (int i=0;i<4;i++) acc[m][n][i]=0.f;

  mainloop8(g_vh, Dd, g_wh + (size_t)34*WSZ, bBase, nBase, dynU, acc);

  norm_epilogue<true>(acc, biasS, redS, normP, scaleS,
                      out + 4096, XS, x + 4096, XS, bBase, nBase);
}

// =======================================================================
// mix: attn = q.kc; vh = fp16(l2norm(xc*attn + sum_w ap*xp_w + an*xn_w))
// =======================================================================
__global__ void mix_kernel(const float* __restrict__ x,
                           const float* __restrict__ dotP)
{
  __shared__ float sb[4];
  const int b = blockIdx.x, t = threadIdx.x;
  const __half* xhr = g_xh + (size_t)b*XS;

  uint2 qv = *(const uint2*)(g_qh + (size_t)b*Dd + t*4);
  uint2 kv = *(const uint2*)(g_qh + (size_t)(Bsz + b)*Dd + t*4);
  float2 qa = __half22float2(*(__half2*)&qv.x);
  float2 qb = __half22float2(*(__half2*)&qv.y);
  float2 ka = __half22float2(*(__half2*)&kv.x);
  float2 kb = __half22float2(*(__half2*)&kv.y);
  float part = qa.x*ka.x + qa.y*ka.y + qb.x*kb.x + qb.y*kb.y;
  #pragma unroll
  for (int o=16;o;o>>=1) part += __shfl_xor_sync(0xffffffffu, part, o);
  if ((t & 31) == 0) sb[t>>5] = part;
  __syncthreads();
  const float attn = sb[0] + sb[1] + sb[2] + sb[3];
  __syncthreads();

  float4 xc4 = ((const float4*)(x + (size_t)b*XS + 4096))[t];
  float4 acc;
  acc.x = xc4.x*attn; acc.y = xc4.y*attn; acc.z = xc4.z*attn; acc.w = xc4.w*attn;
  #pragma unroll
  for (int w=0;w<8;w++){
    float4 pa = *(const float4*)(dotP + ((size_t)w*Bsz + b)*4);
    float aw = pa.x + pa.y + pa.z + pa.w;
    uint2 up = *(const uint2*)(xhr + w*512 + t*4);
    float2 p0 = __half22float2(*(__half2*)&up.x);
    float2 p1 = __half22float2(*(__half2*)&up.y);
    acc.x += aw*p0.x; acc.y += aw*p0.y; acc.z += aw*p1.x; acc.w += aw*p1.y;
    float4 pn = *(const float4*)(dotP + ((size_t)(8+w)*Bsz + b)*4);
    float nw = pn.x + pn.y + pn.z + pn.w;
    uint2 un = *(const uint2*)(xhr + (9+w)*512 + t*4);
    float2 n0 = __half22float2(*(__half2*)&un.x);
    float2 n1 = __half22float2(*(__half2*)&un.y);
    acc.x += nw*n0.x; acc.y += nw*n0.y; acc.z += nw*n1.x; acc.w += nw*n1.y;
  }
  float ss = acc.x*acc.x + acc.y*acc.y + acc.z*acc.z + acc.w*acc.w;
  #pragma unroll
  for (int o=16;o;o>>=1) ss += __shfl_xor_sync(0xffffffffu, ss, o);
  if ((t & 31) == 0) sb[t>>5] = ss;
  __syncthreads();
  float tot = sb[0] + sb[1] + sb[2] + sb[3];
  float sc = 1.f / fmaxf(sqrtf(tot), 1e-12f);
  __half2 h0 = __floats2half2_rn(acc.x*sc, acc.y*sc);
  __half2 h1 = __floats2half2_rn(acc.z*sc, acc.w*sc);
  uint2 o; o.x = *(uint32_t*)&h0; o.y = *(uint32_t*)&h1;
  *(uint2*)(g_vh + (size_t)b*Dd + t*4) = o;
}

// =======================================================================
extern "C" void kernel_launch(void* const* d_in, const int* in_sizes, int n_in,
                              void* d_out, int out_size)
{
  const float* x   = (const float*)d_in[0];
  const float* Wq  = (const float*)d_in[1];
  const float* bq  = (const float*)d_in[2];
  const float* Wkc = (const float*)d_in[3];
  const float* bkc = (const float*)d_in[4];
  const float* Wkp = (const float*)d_in[5];
  const float* bkp = (const float*)d_in[6];
  const float* Wkn = (const float*)d_in[7];
  const float* bkn = (const float*)d_in[8];
  const float* Wfp = (const float*)d_in[9];
  const float* bfp = (const float*)d_in[10];
  const float* Wfn = (const float*)d_in[11];
  const float* bfn = (const float*)d_in[12];
  const float* Wfc = (const float*)d_in[13];
  const float* bfc = (const float*)d_in[14];
  float* out = (float*)d_out;

  float *dotP;
  cudaGetSymbolAddress((void**)&dotP, s_dotP);

  cudaFuncSetAttribute(hgemm_store, cudaFuncAttributeMaxDynamicSharedMemorySize, DYN_SMEM);
  cudaFuncSetAttribute(hgemm_dn,    cudaFuncAttributeMaxDynamicSharedMemorySize, DYN_SMEM);
  cudaFuncSetAttribute(hgemm_fc,    cudaFuncAttributeMaxDynamicSharedMemorySize, DYN_SMEM);

  // side stream + events, created once (host-side objects; per-call work identical)
  static cudaStream_t s2 = nullptr;
  static cudaEvent_t evFork = nullptr, evJoin = nullptr;
  if (!s2){
    cudaStreamCreateWithFlags(&s2, cudaStreamNonBlocking);
    cudaEventCreateWithFlags(&evFork, cudaEventDisableTiming);
    cudaEventCreateWithFlags(&evJoin, cudaEventDisableTiming);
  }

  const int xBlocks = (Bsz*XS/8)/256;          // 34816
  const int wPer    = (WSZ/8)/256;             // 128 blocks per weight matrix

  // [0] x + Wq + Wkc -> fp16 (main stream)
  cvtPre<<<xBlocks + 2*wPer, 256>>>(x, Wq, Wkc);

  // fork: convert remaining 33 weights on s2, concurrent with hgemm_store
  cudaEventRecord(evFork, 0);
  cudaStreamWaitEvent(s2, evFork, 0);
  cvtWrest<<<33*wPer, 256, 0, s2>>>(Wkp, Wkn, Wfp, Wfn, Wfc);
  cudaEventRecord(evJoin, s2);

  // [1] q / kc (fp16 outputs) — overlaps cvtWrest
  hgemm_store<<<dim3(64,4,2), 128, DYN_SMEM>>>(bq, bkc);

  // join: dn needs W2..W34
  cudaStreamWaitEvent(0, evJoin, 0);

  // [2] paired DOT+NORM per window slot
  hgemm_dn<<<dim3(64,4,16), 128, DYN_SMEM>>>(bkp, bkn, bfp, bfn, dotP, out);

  // [3] mix -> vh (fp16 direct)
  mix_kernel<<<Bsz, 128>>>(x, dotP);

  // [4] fc (+ residual xc), cluster-fused norm
  hgemm_fc<<<dim3(64,4,1), 128, DYN_SMEM>>>(bfc, x, out);
}

// round 14
// speedup vs baseline: 1.2910x; 1.0879x over previous
#include <cuda_runtime.h>
#include <cuda_fp16.h>
#include <cstdint>

#define Bsz 8192
#define Dd  512
#define XS  8704           // 17*512 row stride of x / out
#define WSZ 262144         // 512*512 per weight matrix
#define NW  35
#define STG 32768          // per-stage smem: A 16K + B 16K
#define DYN_SMEM (3*STG + 1024)

// ---------------- device scratch (allocation-free rule) ----------------
__device__ __align__(256) __half g_xh[Bsz*XS];
__device__ __align__(256) __half g_wh[NW*WSZ];
__device__ __align__(256) __half g_vh[Bsz*Dd];
__device__ __align__(256) __half g_qh[2*Bsz*Dd];     // q then kc (fp16)
__device__ __align__(256) float  s_dotP[16*Bsz*4];   // [z][b][ctaN]

// ---------------- ptx helpers ----------------
__device__ __forceinline__ uint32_t smem_u32(const void* p){
  uint32_t a;
  asm("{ .reg .u64 t; cvta.to.shared.u64 t, %1; cvt.u32.u64 %0, t; }" : "=r"(a) : "l"(p));
  return a;
}
#define CP16(s,g) asm volatile("cp.async.cg.shared.global [%0], [%1], 16;" :: "r"(s), "l"(g))
#define CPCOMMIT() asm volatile("cp.async.commit_group;" ::: "memory")
#define CPWAIT1()  asm volatile("cp.async.wait_group 1;" ::: "memory")
#define CLUSTER_ARRIVE() asm volatile("barrier.cluster.arrive.aligned;" ::: "memory")
#define CLUSTER_WAIT()   asm volatile("barrier.cluster.wait.aligned;" ::: "memory")

__device__ __forceinline__ void ldsm4(uint32_t* r, uint32_t a){
  asm volatile("ldmatrix.sync.aligned.m8n8.x4.shared.b16 {%0,%1,%2,%3}, [%4];"
    : "=r"(r[0]),"=r"(r[1]),"=r"(r[2]),"=r"(r[3]) : "r"(a));
}
#define MMA(c,a,b0,b1) \
  asm volatile("mma.sync.aligned.m16n8k16.row.col.f32.f16.f16.f32 " \
    "{%0,%1,%2,%3},{%4,%5,%6,%7},{%8,%9},{%0,%1,%2,%3};" \
    : "+f"((c)[0]),"+f"((c)[1]),"+f"((c)[2]),"+f"((c)[3]) \
    : "r"((a)[0]),"r"((a)[1]),"r"((a)[2]),"r"((a)[3]),"r"(b0),"r"(b1))

#define SWZ(o) ((o) ^ (((o) >> 3) & 0x70))

// ---------------- fp32 -> fp16 conversion ----------------
__device__ __forceinline__ void cvt8core(const float* __restrict__ s, size_t i,
                                         __half* __restrict__ h){
  float4 a = ((const float4*)s)[2*i], b = ((const float4*)s)[2*i+1];
  __half2 H[4];
  H[0] = __half2(__float2half_rn(a.x), __float2half_rn(a.y));
  H[1] = __half2(__float2half_rn(a.z), __float2half_rn(a.w));
  H[2] = __half2(__float2half_rn(b.x), __float2half_rn(b.y));
  H[3] = __half2(__float2half_rn(b.z), __float2half_rn(b.w));
  ((uint4*)h)[i] = *(uint4*)H;
}

// x + Wq + Wkc (everything hgemm_store needs)
__global__ void cvtPre(const float* __restrict__ x,
                       const float* __restrict__ Wq, const float* __restrict__ Wkc){
  const int xB = (Bsz*XS/8)/256;   // 34816
  const int bid = blockIdx.x;
  if (bid < xB){
    int i = bid*256 + threadIdx.x;
    cvt8core(x, i, g_xh);
  } else {
    int i = (bid - xB)*256 + threadIdx.x;
    int w = i >> 15, j = i & 32767;
    const float* src = (w == 0) ? Wq : Wkc;
    cvt8core(src, j, g_wh + (size_t)w*WSZ);
  }
}

// W2..W34 (33 matrices) — side stream
__global__ void cvtWrest(const float* __restrict__ Wkp, const float* __restrict__ Wkn,
                         const float* __restrict__ Wfp, const float* __restrict__ Wfn,
                         const float* __restrict__ Wfc){
  int i = blockIdx.x*256 + threadIdx.x;
  int w = (i >> 15) + 2;           // 2..34
  int j = i & 32767;
  const float* src;
  if      (w < 10)  src = Wkp + (size_t)(w-2)*WSZ;
  else if (w < 18)  src = Wkn + (size_t)(w-10)*WSZ;
  else if (w < 26)  src = Wfp + (size_t)(w-18)*WSZ;
  else if (w < 34)  src = Wfn + (size_t)(w-26)*WSZ;
  else              src = Wfc;
  cvt8core(src, j, g_wh + (size_t)w*WSZ);
}

// =======================================================================
// building blocks — 128-thread CTA, 4 warps, warp tile 64x64 (2M x 2N)
// =======================================================================
__device__ __forceinline__ void load_chunk(const __half* __restrict__ Ah, int lda,
                                           const __half* __restrict__ Wh,
                                           int bBase, int nBase, int kc,
                                           uint32_t base, int tid){
  const int kOff = kc * 64;
  #pragma unroll
  for (int i=0;i<8;i++){
    int idx = i*128 + tid, row = idx>>3, g = idx&7;
    uint32_t sw = SWZ((uint32_t)(row*128 + g*16));
    CP16(base + sw,         Ah + (size_t)(bBase+row)*(size_t)lda + kOff + g*8);
    CP16(base + 16384 + sw, Wh + (size_t)(nBase+row)*Dd + kOff + g*8);
  }
}

__device__ __forceinline__ void frag_setup(uint32_t (&aRowOff)[4], uint32_t (&bRowOff)[4],
                                           uint32_t (&selA)[4], uint32_t (&selB)[4]){
  const int tid = threadIdx.x, lane = tid & 31, wid = tid >> 5;
  const int warpM = wid >> 1, warpN = wid & 1;
  #pragma unroll
  for (int i=0;i<4;i++)
    aRowOff[i] = (uint32_t)((warpM*64 + i*16 + (lane&15)) * 128);
  #pragma unroll
  for (int i=0;i<4;i++)
    bRowOff[i] = (uint32_t)((warpN*64 + i*16 + (lane&7) + ((lane&16)>>1)) * 128);
  const int aXb = lane >> 4, bXb = (lane >> 3) & 1, lx = lane & 7;
  #pragma unroll
  for (int q=0;q<4;q++){
    selA[q] = (uint32_t)(((2*q + aXb) ^ lx) << 4);
    selB[q] = (uint32_t)(((2*q + bXb) ^ lx) << 4);
  }
}

__device__ __forceinline__ void compute_chunk(uint32_t aB, uint32_t bB,
    const uint32_t (&aRowOff)[4], const uint32_t (&bRowOff)[4],
    const uint32_t (&selA)[4], const uint32_t (&selB)[4],
    float (&acc)[4][8][4]){
  uint32_t aF[2][4][4], bF[2][2][4];
  #pragma unroll
  for (int m=0;m<4;m++) ldsm4(aF[0][m], aB + aRowOff[m] + selA[0]);
  ldsm4(bF[0][0], bB + bRowOff[0] + selB[0]);
  ldsm4(bF[0][1], bB + bRowOff[1] + selB[0]);
  #pragma unroll
  for (int q=0;q<4;q++){
    const int cur = q&1, nxt = cur^1;
    ldsm4(bF[1][0], bB + bRowOff[2] + selB[q]);
    ldsm4(bF[1][1], bB + bRowOff[3] + selB[q]);
    #pragma unroll
    for (int mt=0;mt<4;mt++)
      #pragma unroll
      for (int j=0;j<2;j++){
        MMA(acc[mt][j*2],   aF[cur][mt], bF[0][j][0], bF[0][j][1]);
        MMA(acc[mt][j*2+1], aF[cur][mt], bF[0][j][2], bF[0][j][3]);
      }
    if (q < 3){
      #pragma unroll
      for (int m=0;m<4;m++) ldsm4(aF[nxt][m], aB + aRowOff[m] + selA[q+1]);
      ldsm4(bF[0][0], bB + bRowOff[0] + selB[q+1]);
      ldsm4(bF[0][1], bB + bRowOff[1] + selB[q+1]);
    }
    #pragma unroll
    for (int mt=0;mt<4;mt++)
      #pragma unroll
      for (int j=0;j<2;j++){
        MMA(acc[mt][4+j*2],   aF[cur][mt], bF[1][j][0], bF[1][j][1]);
        MMA(acc[mt][4+j*2+1], aF[cur][mt], bF[1][j][2], bF[1][j][3]);
      }
  }
}

__device__ __forceinline__ void mainloop8(const __half* __restrict__ Ah, int lda,
                                          const __half* __restrict__ Wh,
                                          int bBase, int nBase, uint32_t dynU,
                                          float (&acc)[4][8][4]){
  const int tid = threadIdx.x;
  uint32_t aRowOff[4], bRowOff[4], selA[4], selB[4];
  frag_setup(aRowOff, bRowOff, selA, selB);
  load_chunk(Ah, lda, Wh, bBase, nBase, 0, dynU, tid);       CPCOMMIT();
  load_chunk(Ah, lda, Wh, bBase, nBase, 1, dynU + STG, tid); CPCOMMIT();
  #pragma unroll
  for (int s=0;s<8;s++){
    CPWAIT1();
    __syncthreads();
    if (s + 2 < 8) load_chunk(Ah, lda, Wh, bBase, nBase, s+2, dynU + ((s+2)%3)*STG, tid);
    CPCOMMIT();
    const uint32_t aB = dynU + (s%3)*STG;
    compute_chunk(aB, aB + 16384, aRowOff, bRowOff, selA, selB, acc);
  }
}

// NORM epilogue (cluster-fused l2 normalization over 4 N-CTAs)
template<bool RES>
__device__ __forceinline__ void norm_epilogue(
    float (&acc)[4][8][4], const float* biasS,
    float (*redS)[2], float* normP, float* scaleS,
    float* outPtr, int ldo, const float* R, int ldr,
    int bBase, int nBase)
{
  const int tid = threadIdx.x, lane = tid & 31, wid = tid >> 5;
  const int warpM = wid >> 1, warpN = wid & 1;
  #pragma unroll
  for (int mt=0;mt<4;mt++){
    const int rl0 = warpM*64 + mt*16 + (lane>>2);
    const float* r0p = RES ? (R + (size_t)(bBase+rl0)*(size_t)ldr) : nullptr;
    const float* r1p = RES ? (r0p + (size_t)8*(size_t)ldr) : nullptr;
    float s0 = 0.f, s1 = 0.f;
    #pragma unroll
    for (int nt=0;nt<8;nt++){
      const int bl = warpN*64 + nt*8 + ((lane&3)<<1);
      const int c  = nBase + bl;
      float bx = biasS[bl], by = biasS[bl+1];
      float v00 = acc[mt][nt][0]+bx, v01 = acc[mt][nt][1]+by;
      float v10 = acc[mt][nt][2]+bx, v11 = acc[mt][nt][3]+by;
      if (RES){
        float2 ra = *(const float2*)(r0p + c);
        float2 rb = *(const float2*)(r1p + c);
        v00 += ra.x; v01 += ra.y; v10 += rb.x; v11 += rb.y;
      }
      acc[mt][nt][0]=v00; acc[mt][nt][1]=v01;
      acc[mt][nt][2]=v10; acc[mt][nt][3]=v11;
      s0 += v00*v00 + v01*v01;
      s1 += v10*v10 + v11*v11;
    }
    s0 += __shfl_xor_sync(0xffffffffu, s0, 1); s0 += __shfl_xor_sync(0xffffffffu, s0, 2);
    s1 += __shfl_xor_sync(0xffffffffu, s1, 1); s1 += __shfl_xor_sync(0xffffffffu, s1, 2);
    if ((lane&3) == 0){ redS[rl0][warpN] = s0; redS[rl0+8][warpN] = s1; }
  }
  __syncthreads();
  normP[tid] = redS[tid][0] + redS[tid][1];
  CLUSTER_ARRIVE(); CLUSTER_WAIT();
  {
    const uint32_t loc = smem_u32(normP) + (uint32_t)tid*4;
    float tot = 0.f;
    #pragma unroll
    for (int r=0;r<4;r++){
      uint32_t rem; float pv;
      asm volatile("mapa.shared::cluster.u32 %0, %1, %2;" : "=r"(rem) : "r"(loc), "r"(r));
      asm volatile("ld.shared::cluster.f32 %0, [%1];" : "=f"(pv) : "r"(rem));
      tot += pv;
    }
    scaleS[tid] = 1.f / fmaxf(sqrtf(tot), 1e-12f);
  }
  CLUSTER_ARRIVE(); CLUSTER_WAIT();
  __syncthreads();
  #pragma unroll
  for (int mt=0;mt<4;mt++){
    const int rl0 = warpM*64 + mt*16 + (lane>>2);
    const float sc0 = scaleS[rl0], sc1 = scaleS[rl0+8];
    float* o0 = outPtr + (size_t)(bBase+rl0)*(size_t)ldo;
    float* o1 = o0 + (size_t)8*(size_t)ldo;
    #pragma unroll
    for (int nt=0;nt<8;nt++){
      const int c = nBase + warpN*64 + nt*8 + ((lane&3)<<1);
      *(float2*)(o0 + c) = make_float2(acc[mt][nt][0]*sc0, acc[mt][nt][1]*sc0);
      *(float2*)(o1 + c) = make_float2(acc[mt][nt][2]*sc1, acc[mt][nt][3]*sc1);
    }
  }
}

// =======================================================================
// q/kc GEMM -> fp16 output, grid (64,4,2), 128 threads
// =======================================================================
__global__ void __launch_bounds__(128,2) hgemm_store(
    const float* __restrict__ bq, const float* __restrict__ bkc)
{
  const int z = blockIdx.z;
  const __half* Ah = g_xh + 4096;
  const __half* Wh = g_wh + (size_t)z*WSZ;
  const float* bp = (z == 0) ? bq : bkc;
  __half* outPtr = g_qh + (size_t)z*Bsz*Dd;

  const int tid = threadIdx.x, lane = tid & 31, wid = tid >> 5;
  const int warpM = wid >> 1, warpN = wid & 1;
  const int bBase = blockIdx.x * 128, nBase = blockIdx.y * 128;

  extern __shared__ char dsm[];
  const uint32_t dynU = (smem_u32(dsm) + 1023u) & ~1023u;
  __shared__ float biasS[128];
  if (tid < 32) ((float4*)biasS)[tid] = ((const float4*)(bp + nBase))[tid];

  float acc[4][8][4];
  #pragma unroll
  for (int m=0;m<4;m++) for (int n=0;n<8;n++) for (int i=0;i<4;i++) acc[m][n][i]=0.f;

  mainloop8(Ah, XS, Wh, bBase, nBase, dynU, acc);

  #pragma unroll
  for (int mt=0;mt<4;mt++){
    const int rl0 = warpM*64 + mt*16 + (lane>>2);
    __half* o0 = outPtr + (size_t)(bBase+rl0)*Dd;
    __half* o1 = o0 + (size_t)8*Dd;
    #pragma unroll
    for (int nt=0;nt<8;nt++){
      const int bl = warpN*64 + nt*8 + ((lane&3)<<1);
      const int c  = nBase + bl;
      float bx = biasS[bl], by = biasS[bl+1];
      *(__half2*)(o0 + c) = __floats2half2_rn(acc[mt][nt][0]+bx, acc[mt][nt][1]+by);
      *(__half2*)(o1 + c) = __floats2half2_rn(acc[mt][nt][2]+bx, acc[mt][nt][3]+by);
    }
  }
}

// =======================================================================
// DOT kernel (ap/an partials): grid (64,4,16), NO cluster, 128 threads
// =======================================================================
__global__ void __launch_bounds__(128,2) hgemm_dot(
    const float* __restrict__ bkp, const float* __restrict__ bkn,
    float* __restrict__ dotP)
{
  const int zw = blockIdx.z;
  const int widx = zw + (zw >= 8 ? 1 : 0);
  const __half* Ah = g_xh + widx*Dd;
  const __half* Wk = g_wh + (size_t)(2 + zw)*WSZ;
  const float* bp = (zw < 8) ? bkp + (size_t)zw*Dd : bkn + (size_t)(zw-8)*Dd;

  const int tid = threadIdx.x, lane = tid & 31, wid = tid >> 5;
  const int warpM = wid >> 1, warpN = wid & 1;
  const int bBase = blockIdx.x * 128, nBase = blockIdx.y * 128;

  extern __shared__ char dsm[];
  const uint32_t dynU = (smem_u32(dsm) + 1023u) & ~1023u;
  __shared__ float biasS[128];
  __shared__ float redS[128][2];
  if (tid < 32) ((float4*)biasS)[tid] = ((const float4*)(bp + nBase))[tid];

  float acc[4][8][4];
  #pragma unroll
  for (int m=0;m<4;m++) for (int n=0;n<8;n++) for (int i=0;i<4;i++) acc[m][n][i]=0.f;

  mainloop8(Ah, XS, Wk, bBase, nBase, dynU, acc);

  #pragma unroll
  for (int mt=0;mt<4;mt++){
    const int rl0 = warpM*64 + mt*16 + (lane>>2);
    const __half* q0 = g_qh + (size_t)(bBase+rl0)*Dd;
    const __half* q1 = q0 + (size_t)8*Dd;
    float s0 = 0.f, s1 = 0.f;
    #pragma unroll
    for (int nt=0;nt<8;nt++){
      const int bl = warpN*64 + nt*8 + ((lane&3)<<1);
      const int cc = nBase + bl;
      float bx = biasS[bl], by = biasS[bl+1];
      float2 qa = __half22float2(*(const __half2*)(q0 + cc));
      float2 qb = __half22float2(*(const __half2*)(q1 + cc));
      s0 += (acc[mt][nt][0]+bx)*qa.x + (acc[mt][nt][1]+by)*qa.y;
      s1 += (acc[mt][nt][2]+bx)*qb.x + (acc[mt][nt][3]+by)*qb.y;
    }
    s0 += __shfl_xor_sync(0xffffffffu, s0, 1); s0 += __shfl_xor_sync(0xffffffffu, s0, 2);
    s1 += __shfl_xor_sync(0xffffffffu, s1, 1); s1 += __shfl_xor_sync(0xffffffffu, s1, 2);
    if ((lane&3) == 0){ redS[rl0][warpN] = s0; redS[rl0+8][warpN] = s1; }
  }
  __syncthreads();
  {
    float p = redS[tid][0] + redS[tid][1];
    dotP[((size_t)zw*Bsz + bBase + tid)*4 + blockIdx.y] = p;
  }
}

// =======================================================================
// NORM kernel (fp/fn): grid (64,4,16), cluster (1,4,1), 128 threads
// =======================================================================
__global__ void __cluster_dims__(1,4,1) __launch_bounds__(128,2) hgemm_norm(
    const float* __restrict__ bfp, const float* __restrict__ bfn,
    float* __restrict__ out)
{
  const int zw = blockIdx.z;
  const int widx = zw + (zw >= 8 ? 1 : 0);
  const __half* Ah = g_xh + widx*Dd;
  const __half* Wf = g_wh + (size_t)(18 + zw)*WSZ;
  const float* bp = (zw < 8) ? bfp + (size_t)zw*Dd : bfn + (size_t)(zw-8)*Dd;

  const int tid = threadIdx.x;
  const int bBase = blockIdx.x * 128, nBase = blockIdx.y * 128;

  extern __shared__ char dsm[];
  const uint32_t dynU = (smem_u32(dsm) + 1023u) & ~1023u;
  __shared__ float biasS[128];
  __shared__ float redS[128][2];
  __shared__ float normP[128];
  __shared__ float scaleS[128];
  if (tid < 32) ((float4*)biasS)[tid] = ((const float4*)(bp + nBase))[tid];

  float acc[4][8][4];
  #pragma unroll
  for (int m=0;m<4;m++) for (int n=0;n<8;n++) for (int i=0;i<4;i++) acc[m][n][i]=0.f;

  mainloop8(Ah, XS, Wf, bBase, nBase, dynU, acc);

  norm_epilogue<false>(acc, biasS, redS, normP, scaleS,
                       out + (size_t)widx*Dd, XS, nullptr, 0, bBase, nBase);
}

// =======================================================================
// fc GEMM (+residual xc, cluster-fused norm), grid (64,4,1), 128 threads
// =======================================================================
__global__ void __cluster_dims__(1,4,1) __launch_bounds__(128,2) hgemm_fc(
    const float* __restrict__ bfc, const float* __restrict__ x,
    float* __restrict__ out)
{
  const int tid = threadIdx.x;
  const int bBase = blockIdx.x * 128, nBase = blockIdx.y * 128;

  extern __shared__ char dsm[];
  const uint32_t dynU = (smem_u32(dsm) + 1023u) & ~1023u;
  __shared__ float biasS[128];
  __shared__ float redS[128][2];
  __shared__ float normP[128];
  __shared__ float scaleS[128];
  if (tid < 32) ((float4*)biasS)[tid] = ((const float4*)(bfc + nBase))[tid];

  float acc[4][8][4];
  #pragma unroll
  for (int m=0;m<4;m++) for (int n=0;n<8;n++) for (int i=0;i<4;i++) acc[m][n][i]=0.f;

  mainloop8(g_vh, Dd, g_wh + (size_t)34*WSZ, bBase, nBase, dynU, acc);

  norm_epilogue<true>(acc, biasS, redS, normP, scaleS,
                      out + 4096, XS, x + 4096, XS, bBase, nBase);
}

// =======================================================================
// mix: attn = q.kc; vh = fp16(l2norm(xc*attn + sum_w ap*xp_w + an*xn_w))
// =======================================================================
__global__ void mix_kernel(const float* __restrict__ x,
                           const float* __restrict__ dotP)
{
  __shared__ float sb[4];
  const int b = blockIdx.x, t = threadIdx.x;
  const __half* xhr = g_xh + (size_t)b*XS;

  uint2 qv = *(const uint2*)(g_qh + (size_t)b*Dd + t*4);
  uint2 kv = *(const uint2*)(g_qh + (size_t)(Bsz + b)*Dd + t*4);
  float2 qa = __half22float2(*(__half2*)&qv.x);
  float2 qb = __half22float2(*(__half2*)&qv.y);
  float2 ka = __half22float2(*(__half2*)&kv.x);
  float2 kb = __half22float2(*(__half2*)&kv.y);
  float part = qa.x*ka.x + qa.y*ka.y + qb.x*kb.x + qb.y*kb.y;
  #pragma unroll
  for (int o=16;o;o>>=1) part += __shfl_xor_sync(0xffffffffu, part, o);
  if ((t & 31) == 0) sb[t>>5] = part;
  __syncthreads();
  const float attn = sb[0] + sb[1] + sb[2] + sb[3];
  __syncthreads();

  float4 xc4 = ((const float4*)(x + (size_t)b*XS + 4096))[t];
  float4 acc;
  acc.x = xc4.x*attn; acc.y = xc4.y*attn; acc.z = xc4.z*attn; acc.w = xc4.w*attn;
  #pragma unroll
  for (int w=0;w<8;w++){
    float4 pa = *(const float4*)(dotP + ((size_t)w*Bsz + b)*4);
    float aw = pa.x + pa.y + pa.z + pa.w;
    uint2 up = *(const uint2*)(xhr + w*512 + t*4);
    float2 p0 = __half22float2(*(__half2*)&up.x);
    float2 p1 = __half22float2(*(__half2*)&up.y);
    acc.x += aw*p0.x; acc.y += aw*p0.y; acc.z += aw*p1.x; acc.w += aw*p1.y;
    float4 pn = *(const float4*)(dotP + ((size_t)(8+w)*Bsz + b)*4);
    float nw = pn.x + pn.y + pn.z + pn.w;
    uint2 un = *(const uint2*)(xhr + (9+w)*512 + t*4);
    float2 n0 = __half22float2(*(__half2*)&un.x);
    float2 n1 = __half22float2(*(__half2*)&un.y);
    acc.x += nw*n0.x; acc.y += nw*n0.y; acc.z += nw*n1.x; acc.w += nw*n1.y;
  }
  float ss = acc.x*acc.x + acc.y*acc.y + acc.z*acc.z + acc.w*acc.w;
  #pragma unroll
  for (int o=16;o;o>>=1) ss += __shfl_xor_sync(0xffffffffu, ss, o);
  if ((t & 31) == 0) sb[t>>5] = ss;
  __syncthreads();
  float tot = sb[0] + sb[1] + sb[2] + sb[3];
  float sc = 1.f / fmaxf(sqrtf(tot), 1e-12f);
  __half2 h0 = __floats2half2_rn(acc.x*sc, acc.y*sc);
  __half2 h1 = __floats2half2_rn(acc.z*sc, acc.w*sc);
  uint2 o; o.x = *(uint32_t*)&h0; o.y = *(uint32_t*)&h1;
  *(uint2*)(g_vh + (size_t)b*Dd + t*4) = o;
}

// =======================================================================
extern "C" void kernel_launch(void* const* d_in, const int* in_sizes, int n_in,
                              void* d_out, int out_size)
{
  const float* x   = (const float*)d_in[0];
  const float* Wq  = (const float*)d_in[1];
  const float* bq  = (const float*)d_in[2];
  const float* Wkc = (const float*)d_in[3];
  const float* bkc = (const float*)d_in[4];
  const float* Wkp = (const float*)d_in[5];
  const float* bkp = (const float*)d_in[6];
  const float* Wkn = (const float*)d_in[7];
  const float* bkn = (const float*)d_in[8];
  const float* Wfp = (const float*)d_in[9];
  const float* bfp = (const float*)d_in[10];
  const float* Wfn = (const float*)d_in[11];
  const float* bfn = (const float*)d_in[12];
  const float* Wfc = (const float*)d_in[13];
  const float* bfc = (const float*)d_in[14];
  float* out = (float*)d_out;

  float *dotP;
  cudaGetSymbolAddress((void**)&dotP, s_dotP);

  cudaFuncSetAttribute(hgemm_store, cudaFuncAttributeMaxDynamicSharedMemorySize, DYN_SMEM);
  cudaFuncSetAttribute(hgemm_dot,   cudaFuncAttributeMaxDynamicSharedMemorySize, DYN_SMEM);
  cudaFuncSetAttribute(hgemm_norm,  cudaFuncAttributeMaxDynamicSharedMemorySize, DYN_SMEM);
  cudaFuncSetAttribute(hgemm_fc,    cudaFuncAttributeMaxDynamicSharedMemorySize, DYN_SMEM);

  static cudaStream_t s2 = nullptr;
  static cudaEvent_t evFork = nullptr, evW = nullptr, evXh = nullptr, evNorm = nullptr;
  if (!s2){
    cudaStreamCreateWithFlags(&s2, cudaStreamNonBlocking);
    cudaEventCreateWithFlags(&evFork, cudaEventDisableTiming);
    cudaEventCreateWithFlags(&evW,    cudaEventDisableTiming);
    cudaEventCreateWithFlags(&evXh,   cudaEventDisableTiming);
    cudaEventCreateWithFlags(&evNorm, cudaEventDisableTiming);
  }

  const int xBlocks = (Bsz*XS/8)/256;          // 34816
  const int wPer    = (WSZ/8)/256;             // 128 blocks per weight matrix

  // fork side stream at graph root
  cudaEventRecord(evFork, 0);
  cudaStreamWaitEvent(s2, evFork, 0);

  // s2: convert W2..W34 (independent of x)
  cvtWrest<<<33*wPer, 256, 0, s2>>>(Wkp, Wkn, Wfp, Wfn, Wfc);
  cudaEventRecord(evW, s2);

  // main: x + Wq + Wkc -> fp16, then q/kc GEMM
  cvtPre<<<xBlocks + 2*wPer, 256>>>(x, Wq, Wkc);
  cudaEventRecord(evXh, 0);
  hgemm_store<<<dim3(64,4,2), 128, DYN_SMEM>>>(bq, bkc);

  // s2: NORM (needs xh + Wf) — runs concurrent with store/DOT/mix/fc
  cudaStreamWaitEvent(s2, evXh, 0);
  hgemm_norm<<<dim3(64,4,16), 128, DYN_SMEM, s2>>>(bfp, bfn, out);
  cudaEventRecord(evNorm, s2);

  // main: DOT (needs Wk from s2) -> mix -> fc
  cudaStreamWaitEvent(0, evW, 0);
  hgemm_dot<<<dim3(64,4,16), 128, DYN_SMEM>>>(bkp, bkn, dotP);
  mix_kernel<<<Bsz, 128>>>(x, dotP);
  hgemm_fc<<<dim3(64,4,1), 128, DYN_SMEM>>>(bfc, x, out);

  // join: graph completion requires NORM too
  cudaStreamWaitEvent(0, evNorm, 0);
}